// round 14
// baseline (speedup 1.0000x reference)
#include <cuda_runtime.h>
#include <cuda_fp16.h>
#include <math.h>
#include <stdint.h>

// Problem constants
#define BB     2
#define TT     2048
#define CC     2048
#define NHH    16
#define HDD    128
#define NQKV   6144          // 3*C
#define MROWS  4096          // B*T

// Scratch (device globals; no allocation allowed)
__device__ __half g_qkvh[(size_t)MROWS * NQKV];     // 48 MB (q,k roped; v raw)
__device__ __half g_yh[(size_t)MROWS * CC];         // 16 MB
__device__ __half g_xh[(size_t)MROWS * CC];         // 16 MB
__device__ __half g_wah[(size_t)NQKV * CC];         // 24 MB
__device__ __half g_wph[(size_t)CC * CC];           // 8 MB
__device__ float2 g_rope[TT * 64];                  // cos/sin table [t][i]

#define NEG_INF (__int_as_float(0xff800000))

// mma.sync m16n8k16 fp16 -> fp32 acc (in-place)
#define MMA_F16(d, a, b) \
    asm volatile("mma.sync.aligned.m16n8k16.row.col.f32.f16.f16.f32 " \
        "{%0,%1,%2,%3}, {%4,%5,%6,%7}, {%8,%9}, {%0,%1,%2,%3};" \
        : "+f"((d)[0]), "+f"((d)[1]), "+f"((d)[2]), "+f"((d)[3]) \
        : "r"((a)[0]), "r"((a)[1]), "r"((a)[2]), "r"((a)[3]), \
          "r"((b)[0]), "r"((b)[1]))

// ldmatrix x4 (non-transposed)
#define LDSM_X4(r0, r1, r2, r3, addr) \
    asm volatile("ldmatrix.sync.aligned.m8n8.x4.shared.b16 {%0,%1,%2,%3}, [%4];" \
        : "=r"(r0), "=r"(r1), "=r"(r2), "=r"(r3) : "r"(addr))

// ldmatrix x4 transposed (for V in [token][d] layout -> B fragments)
#define LDSM_X4_T(r0, r1, r2, r3, addr) \
    asm volatile("ldmatrix.sync.aligned.m8n8.x4.trans.shared.b16 {%0,%1,%2,%3}, [%4];" \
        : "=r"(r0), "=r"(r1), "=r"(r2), "=r"(r3) : "r"(addr))

__device__ __forceinline__ void cp_async16(uint32_t saddr, const void* gptr) {
    asm volatile("cp.async.cg.shared.global [%0], [%1], 16;"
                 :: "r"(saddr), "l"(gptr));
}
#define CP_COMMIT() asm volatile("cp.async.commit_group;" ::: "memory")
#define CP_WAIT(n)  asm volatile("cp.async.wait_group %0;" :: "n"(n) : "memory")

__device__ __forceinline__ uint32_t smem_u32(const void* p) {
    uint32_t a;
    asm("{ .reg .u64 t; cvta.to.shared.u64 t, %1; cvt.u32.u64 %0, t; }"
        : "=r"(a) : "l"(p));
    return a;
}

__device__ __forceinline__ uint32_t pack_h2(float lo, float hi) {
    __half2 h = __floats2half2_rn(lo, hi);
    return *(uint32_t*)&h;
}

// ---------------------------------------------------------------------------
// fp32 -> fp16 rounding pre-pass
// ---------------------------------------------------------------------------
__global__ void f2h_kernel(const float2* __restrict__ in,
                           __half2* __restrict__ outp, int n2)
{
    int i = blockIdx.x * blockDim.x + threadIdx.x;
    if (i >= n2) return;
    float2 v = in[i];
    outp[i] = __floats2half2_rn(v.x, v.y);
}

// ---------------------------------------------------------------------------
// RoPE cos/sin table
// ---------------------------------------------------------------------------
__global__ void rope_table_kernel(float2* __restrict__ tab)
{
    int idx = blockIdx.x * blockDim.x + threadIdx.x;
    if (idx >= TT * 64) return;
    int tpos = idx >> 6;
    int i    = idx & 63;
    float theta = 1.0f / powf(10000.0f, (float)i / 64.0f);
    float ang   = (float)tpos * theta;
    float2 cs;
    cs.x = cosf(ang);
    cs.y = sinf(ang);
    tab[idx] = cs;
}

// ---------------------------------------------------------------------------
// FP16 tensor-core GEMM, cp.async 3-stage, CTA 128x128, warp 32x64, BK=64.
// Grouped CTA rasterization (GROUP by-rows per bx sweep) for L2 locality.
// ---------------------------------------------------------------------------
#define PITCH2 36                         // u32 per row (32 data + 4 pad)
#define TILE2_U32 (128 * PITCH2)
#define STAGE2_U32 (2 * TILE2_U32)
#define NSTAGE 3
#define GEMM_SMEM_BYTES (NSTAGE * STAGE2_U32 * 4)   // 110592
#define RGROUP 16

__global__ void __launch_bounds__(256, 2) gemm_h_kernel(
    const __half* __restrict__ A, const __half* __restrict__ W,
    const float* __restrict__ bias, void* __restrict__ outv,
    const float2* __restrict__ rope, int qkv_mode,
    int M, int N, int K)
{
    extern __shared__ __align__(16) uint32_t gsm[];
    const uint32_t sbase = smem_u32(gsm);

    const int t = threadIdx.x, lane = t & 31, wid = t >> 5;
    const int wm = wid & 3, wn = wid >> 2;
    const int g = lane >> 2, c = lane & 3;

    // grouped rasterization: concurrent CTAs cover a ~RGROUP x (n/RGROUP)
    // block of tiles instead of a 1 x n stripe.
    int bx, by;
    {
        const int gx = gridDim.x;
        const int bid = blockIdx.y * gx + blockIdx.x;
        const int width = gx * RGROUP;
        const int band = bid / width;
        const int rem  = bid % width;
        by = band * RGROUP + (rem % RGROUP);
        bx = rem / RGROUP;
    }
    const int m0 = by * 128, n0 = bx * 128;

    const int quad   = lane >> 3;
    const int lrow_a = (lane & 7) + ((quad & 1) << 3);
    const int kseg_a = (quad >> 1) << 2;
    const int lrow_b = (lane & 7) + ((quad >> 1) << 3);
    const int kseg_b = (quad & 1) << 2;

    const int lrow = t >> 3;             // loader row 0..31
    const int lch  = t & 7;              // loader 16B chunk

    const __half* Ab = A + (size_t)m0 * K;
    const __half* Wb = W + (size_t)n0 * K;

    float acc[2][8][4];
#pragma unroll
    for (int i = 0; i < 2; i++)
#pragma unroll
        for (int j = 0; j < 8; j++)
#pragma unroll
            for (int r = 0; r < 4; r++) acc[i][j][r] = 0.f;

    const int nsteps = K >> 6;           // BK = 64 halves

    auto issue_stage = [&](int s, int kk) {
        const uint32_t sA = sbase + (uint32_t)(s * STAGE2_U32) * 4;
        const uint32_t sB = sA + TILE2_U32 * 4;
        const int kof = kk * 64 + lch * 8;
#pragma unroll
        for (int i = 0; i < 4; i++) {
            const int row = lrow + i * 32;
            cp_async16(sA + (row * PITCH2 + lch * 4) * 4, Ab + (size_t)row * K + kof);
            cp_async16(sB + (row * PITCH2 + lch * 4) * 4, Wb + (size_t)row * K + kof);
        }
        CP_COMMIT();
    };

    issue_stage(0, 0);
    issue_stage(1, 1);

    for (int j = 0; j < nsteps; j++) {
        const int cur = j % NSTAGE;
        CP_WAIT(1);
        __syncthreads();    // stage j visible AND all warps done with buffer (j+2)%3
        if (j + 2 < nsteps) issue_stage((j + 2) % NSTAGE, j + 2);

        const uint32_t sAb = sbase + (uint32_t)(cur * STAGE2_U32) * 4;
        const uint32_t sBb = sAb + TILE2_U32 * 4;
#pragma unroll
        for (int ks = 0; ks < 4; ks++) {          // 4 x k16
            const int kc = ks * 8;
            uint32_t a[2][4];
#pragma unroll
            for (int mt = 0; mt < 2; mt++) {
                const uint32_t ad = sAb +
                    (uint32_t)(((wm * 32 + mt * 16 + lrow_a) * PITCH2) + kc + kseg_a) * 4;
                LDSM_X4(a[mt][0], a[mt][1], a[mt][2], a[mt][3], ad);
            }
            uint32_t bfr[8][2];
#pragma unroll
            for (int p = 0; p < 4; p++) {
                const uint32_t bd = sBb +
                    (uint32_t)(((wn * 64 + p * 16 + lrow_b) * PITCH2) + kc + kseg_b) * 4;
                LDSM_X4(bfr[2 * p][0], bfr[2 * p][1],
                        bfr[2 * p + 1][0], bfr[2 * p + 1][1], bd);
            }
#pragma unroll
            for (int mt = 0; mt < 2; mt++)
#pragma unroll
                for (int nf = 0; nf < 8; nf++)
                    MMA_F16(acc[mt][nf], a[mt], bfr[nf]);
        }
    }

    // epilogue
#pragma unroll
    for (int mt = 0; mt < 2; mt++) {
        const int r0 = m0 + wm * 32 + mt * 16 + g;
        const int tp0 = r0 & (TT - 1);
        const int tp1 = (r0 + 8) & (TT - 1);
#pragma unroll
        for (int nf = 0; nf < 8; nf++) {
            const int col = n0 + wn * 64 + nf * 8 + c * 2;
            const float b0v = bias[col], b1v = bias[col + 1];
            float v00 = acc[mt][nf][0] + b0v;
            float v01 = acc[mt][nf][1] + b1v;
            float v10 = acc[mt][nf][2] + b0v;
            float v11 = acc[mt][nf][3] + b1v;
            if (qkv_mode) {
                if (col < 2 * CC) {
                    const int i = (col & (HDD - 1)) >> 1;
                    const float2 cs0 = rope[tp0 * 64 + i];
                    const float2 cs1 = rope[tp1 * 64 + i];
                    float e0 = v00 * cs0.x - v01 * cs0.y;
                    float o0 = v00 * cs0.y + v01 * cs0.x;
                    float e1 = v10 * cs1.x - v11 * cs1.y;
                    float o1 = v10 * cs1.y + v11 * cs1.x;
                    v00 = e0; v01 = o0; v10 = e1; v11 = o1;
                }
                __half* outh = (__half*)outv;
                *(uint32_t*)(outh + (size_t)r0 * N + col)       = pack_h2(v00, v01);
                *(uint32_t*)(outh + (size_t)(r0 + 8) * N + col) = pack_h2(v10, v11);
            } else {
                float* outf = (float*)outv;
                float* o0p = outf + (size_t)r0 * N + col;
                float* o1p = outf + (size_t)(r0 + 8) * N + col;
                o0p[0] = v00; o0p[1] = v01;
                o1p[0] = v10; o1p[1] = v11;
            }
        }
    }
}

// ---------------------------------------------------------------------------
// Flash attention: Q-tile 64, 256 threads, 2 CTAs/SM.
// K double-buffered (prefetch next tile during softmax/PV).
// V in natural [token][d] layout; PV B-frags via ldmatrix.trans.
// ---------------------------------------------------------------------------
#define FQP2 68    // u32 pitch for Q/K/V rows (64 data + 4)
#define FVP2 36    // u32 pitch for P rows (32 data + 4)
#define FL_T_U32  (64 * FQP2)     // 4352 (one 64x128 half tile)
#define FL_S_U32  (64 * FVP2)     // 2304
#define FL_STATS  (6 * 64)
#define FLASH_SMEM_U32 (4 * FL_T_U32 + FL_S_U32 + FL_STATS)   // Q,K0,K1,V + S + stats
#define FLASH_SMEM_BYTES (FLASH_SMEM_U32 * 4)    // ~80.4 KB

__global__ void __launch_bounds__(256, 2) flash_h_kernel(
    const __half* __restrict__ qkvh, __half* __restrict__ y)
{
    extern __shared__ uint32_t fsm[];
    uint32_t* Ssu = fsm + 4 * FL_T_U32;
    float* pmax = (float*)(Ssu + FL_S_U32);
    float* psum = pmax + 2 * 64;
    float* mrow = psum + 2 * 64;
    float* lrow = mrow + 64;

    const uint32_t Qsb = smem_u32(fsm);
    const uint32_t K0b = Qsb + FL_T_U32 * 4;
    const uint32_t K1b = K0b + FL_T_U32 * 4;
    const uint32_t Vb  = K1b + FL_T_U32 * 4;
    const uint32_t Ssb = Vb + FL_T_U32 * 4;

    const int bh = blockIdx.y, b = bh >> 4, h = bh & 15;
    const int qt = gridDim.x - 1 - blockIdx.x;    // heavy tiles first
    const int q0 = qt * 64;
    const int t = threadIdx.x, lane = t & 31, wid = t >> 5;
    const int wm = wid & 3, wn = wid >> 2;
    const int g = lane >> 2, c = lane & 3;
    const float scale = 0.08838834764831845f;   // 1/sqrt(128)

    const int quad   = lane >> 3;
    const int lrow_a = (lane & 7) + ((quad & 1) << 3);
    const int kseg_a = (quad >> 1) << 2;
    const int lrow_b = (lane & 7) + ((quad >> 1) << 3);
    const int kseg_b = (quad & 1) << 2;

    // trans-ldmatrix lane mapping for V [token][d]
    const int vrow = lane & 15;
    const int vseg = (lane >> 4) << 2;

    const __half* Qg = qkvh + ((size_t)(b * TT + q0)) * NQKV + h * HDD;
    const __half* Kbase = qkvh + (size_t)b * TT * NQKV + CC + h * HDD;
    const __half* Vbase = Kbase + CC;

    // load Q tile + K(0) tile via cp.async
#pragma unroll
    for (int i = 0; i < 4; i++) {
        const int idx = t + i * 256;
        const int rr = idx >> 4, cc = idx & 15;
        cp_async16(Qsb + (rr * FQP2 + cc * 4) * 4,
                   Qg + (size_t)rr * NQKV + cc * 8);
    }
    CP_COMMIT();
#pragma unroll
    for (int i = 0; i < 4; i++) {
        const int idx = t + i * 256;
        const int rr = idx >> 4, cc = idx & 15;
        cp_async16(K0b + (rr * FQP2 + cc * 4) * 4,
                   Kbase + (size_t)rr * NQKV + cc * 8);
    }
    CP_COMMIT();
    if (t < 64) { mrow[t] = NEG_INF; lrow[t] = 0.f; }

    const int r0 = wm * 16 + g;
    const int qg0 = q0 + r0, qg1 = q0 + r0 + 8;

    float acc_o[8][4];
#pragma unroll
    for (int j = 0; j < 8; j++)
#pragma unroll
        for (int r = 0; r < 4; r++) acc_o[j][r] = 0.f;

    for (int kt = 0; kt <= qt; kt++) {
        const int k0 = kt * 64;
        const uint32_t Kb = (kt & 1) ? K1b : K0b;

        __syncthreads();               // prev iter done with V/Ss; K(kt) buffer safe
        CP_WAIT(0);                    // K(kt) (and Q on iter 0) arrived
        __syncthreads();               // visible to all warps

        // S = Q K^T  (8 x k16 chunks over d=128)
        float acc_s[4][4];
#pragma unroll
        for (int j = 0; j < 4; j++)
#pragma unroll
            for (int r = 0; r < 4; r++) acc_s[j][r] = 0.f;
#pragma unroll
        for (int ks = 0; ks < 8; ks++) {
            const int kc = ks * 8;
            uint32_t a[4];
            {
                const uint32_t ad = Qsb +
                    (uint32_t)(((wm * 16 + lrow_a) * FQP2) + kc + kseg_a) * 4;
                LDSM_X4(a[0], a[1], a[2], a[3], ad);
            }
            uint32_t bf[4][2];
#pragma unroll
            for (int p = 0; p < 2; p++) {
                const uint32_t bd = Kb +
                    (uint32_t)(((wn * 32 + p * 16 + lrow_b) * FQP2) + kc + kseg_b) * 4;
                LDSM_X4(bf[2 * p][0], bf[2 * p][1],
                        bf[2 * p + 1][0], bf[2 * p + 1][1], bd);
            }
#pragma unroll
            for (int nf = 0; nf < 4; nf++)
                MMA_F16(acc_s[nf], a, bf[nf]);
        }

        // scale + causal mask
#pragma unroll
        for (int nf = 0; nf < 4; nf++) {
            const int kg0 = k0 + wn * 32 + nf * 8 + c * 2;
            acc_s[nf][0] = (kg0     <= qg0) ? acc_s[nf][0] * scale : NEG_INF;
            acc_s[nf][1] = (kg0 + 1 <= qg0) ? acc_s[nf][1] * scale : NEG_INF;
            acc_s[nf][2] = (kg0     <= qg1) ? acc_s[nf][2] * scale : NEG_INF;
            acc_s[nf][3] = (kg0 + 1 <= qg1) ? acc_s[nf][3] * scale : NEG_INF;
        }

        // warp-level row max
        float mx0 = NEG_INF, mx1 = NEG_INF;
#pragma unroll
        for (int nf = 0; nf < 4; nf++) {
            mx0 = fmaxf(mx0, fmaxf(acc_s[nf][0], acc_s[nf][1]));
            mx1 = fmaxf(mx1, fmaxf(acc_s[nf][2], acc_s[nf][3]));
        }
        mx0 = fmaxf(mx0, __shfl_xor_sync(0xffffffffu, mx0, 1));
        mx0 = fmaxf(mx0, __shfl_xor_sync(0xffffffffu, mx0, 2));
        mx1 = fmaxf(mx1, __shfl_xor_sync(0xffffffffu, mx1, 1));
        mx1 = fmaxf(mx1, __shfl_xor_sync(0xffffffffu, mx1, 2));
        if (c == 0) {
            pmax[wn * 64 + r0]     = mx0;
            pmax[wn * 64 + r0 + 8] = mx1;
        }
        __syncthreads();               // pmax ready; V buffer free (prev PV done)

        // issue V(kt) load, then prefetch K(kt+1) into the other K buffer
        {
            const __half* Vg = Vbase + (size_t)k0 * NQKV;
#pragma unroll
            for (int i = 0; i < 4; i++) {
                const int idx = t + i * 256;
                const int rr = idx >> 4, cc = idx & 15;
                cp_async16(Vb + (rr * FQP2 + cc * 4) * 4,
                           Vg + (size_t)rr * NQKV + cc * 8);
            }
            CP_COMMIT();
        }
        if (kt < qt) {
            const __half* Kn = Kbase + (size_t)(k0 + 64) * NQKV;
            const uint32_t Ko = (kt & 1) ? K0b : K1b;
#pragma unroll
            for (int i = 0; i < 4; i++) {
                const int idx = t + i * 256;
                const int rr = idx >> 4, cc = idx & 15;
                cp_async16(Ko + (rr * FQP2 + cc * 4) * 4,
                           Kn + (size_t)rr * NQKV + cc * 8);
            }
            CP_COMMIT();
        }

        // combine max, exp, partial sums, write P (fp16)
        const float oldm0 = mrow[r0], oldm1 = mrow[r0 + 8];
        const float mnew0 = fmaxf(oldm0, fmaxf(pmax[r0], pmax[64 + r0]));
        const float mnew1 = fmaxf(oldm1, fmaxf(pmax[r0 + 8], pmax[64 + r0 + 8]));
        const float f0 = __expf(oldm0 - mnew0);
        const float f1 = __expf(oldm1 - mnew1);

        float s0 = 0.f, s1 = 0.f;
#pragma unroll
        for (int nf = 0; nf < 4; nf++) {
            const int cu = wn * 16 + nf * 4 + c;
            float p00 = __expf(acc_s[nf][0] - mnew0);
            float p01 = __expf(acc_s[nf][1] - mnew0);
            float p10 = __expf(acc_s[nf][2] - mnew1);
            float p11 = __expf(acc_s[nf][3] - mnew1);
            s0 += p00 + p01;
            s1 += p10 + p11;
            Ssu[r0 * FVP2 + cu]       = pack_h2(p00, p01);
            Ssu[(r0 + 8) * FVP2 + cu] = pack_h2(p10, p11);
        }
        s0 += __shfl_xor_sync(0xffffffffu, s0, 1);
        s0 += __shfl_xor_sync(0xffffffffu, s0, 2);
        s1 += __shfl_xor_sync(0xffffffffu, s1, 1);
        s1 += __shfl_xor_sync(0xffffffffu, s1, 2);
        if (c == 0) {
            psum[wn * 64 + r0]     = s0;
            psum[wn * 64 + r0 + 8] = s1;
        }
        if (kt < qt) { CP_WAIT(1); }   // V done; K(kt+1) may still fly
        else         { CP_WAIT(0); }
        __syncthreads();               // V + P + psum visible

        if (wn == 0 && c == 0) {
            lrow[r0]     = lrow[r0]     * f0 + psum[r0]     + psum[64 + r0];
            lrow[r0 + 8] = lrow[r0 + 8] * f1 + psum[r0 + 8] + psum[64 + r0 + 8];
            mrow[r0]     = mnew0;
            mrow[r0 + 8] = mnew1;
        }
#pragma unroll
        for (int nf = 0; nf < 8; nf++) {
            acc_o[nf][0] *= f0; acc_o[nf][1] *= f0;
            acc_o[nf][2] *= f1; acc_o[nf][3] *= f1;
        }

        // O += P V   (4 x k16 token-chunks; V B-frags via ldmatrix.trans)
#pragma unroll
        for (int ks = 0; ks < 4; ks++) {
            const int kc = ks * 8;
            uint32_t p[4];
            {
                const uint32_t pd = Ssb +
                    (uint32_t)(((wm * 16 + lrow_a) * FVP2) + kc + kseg_a) * 4;
                LDSM_X4(p[0], p[1], p[2], p[3], pd);
            }
            uint32_t vf[8][2];
#pragma unroll
            for (int db = 0; db < 4; db++) {
                const uint32_t vd = Vb +
                    (uint32_t)(((ks * 16 + vrow) * FQP2) + wn * 32 + db * 8 + vseg) * 4;
                LDSM_X4_T(vf[2 * db][0], vf[2 * db][1],
                          vf[2 * db + 1][0], vf[2 * db + 1][1], vd);
            }
#pragma unroll
            for (int nf = 0; nf < 8; nf++)
                MMA_F16(acc_o[nf], p, vf[nf]);
        }
    }

    __syncthreads();

    // epilogue: divide by l, store fp16 y
    {
        const float li0 = 1.0f / lrow[r0];
        const float li1 = 1.0f / lrow[r0 + 8];
        __half* y0 = y + ((size_t)(b * TT + q0 + r0)) * CC + h * HDD;
        __half* y1 = y + ((size_t)(b * TT + q0 + r0 + 8)) * CC + h * HDD;
#pragma unroll
        for (int nf = 0; nf < 8; nf++) {
            const int col = wn * 64 + nf * 8 + c * 2;
            *(uint32_t*)(y0 + col) = pack_h2(acc_o[nf][0] * li0, acc_o[nf][1] * li0);
            *(uint32_t*)(y1 + col) = pack_h2(acc_o[nf][2] * li1, acc_o[nf][3] * li1);
        }
    }
}

// ---------------------------------------------------------------------------
// Launch
// ---------------------------------------------------------------------------
extern "C" void kernel_launch(void* const* d_in, const int* in_sizes, int n_in,
                              void* d_out, int out_size)
{
    const float* x      = (const float*)d_in[0];   // [2,2048,2048]
    const float* w_att  = (const float*)d_in[1];   // [6144,2048]
    const float* b_att  = (const float*)d_in[2];   // [6144]
    const float* w_proj = (const float*)d_in[3];   // [2048,2048]
    const float* b_proj = (const float*)d_in[4];   // [2048]
    float* out = (float*)d_out;                    // [2,2048,2048]

    __half *qkvh, *yh, *xh, *wah, *wph;
    float2* rope;
    cudaGetSymbolAddress((void**)&qkvh, g_qkvh);
    cudaGetSymbolAddress((void**)&yh,   g_yh);
    cudaGetSymbolAddress((void**)&xh,   g_xh);
    cudaGetSymbolAddress((void**)&wah,  g_wah);
    cudaGetSymbolAddress((void**)&wph,  g_wph);
    cudaGetSymbolAddress((void**)&rope, g_rope);

    cudaFuncSetAttribute(gemm_h_kernel,
                         cudaFuncAttributeMaxDynamicSharedMemorySize,
                         GEMM_SMEM_BYTES);
    cudaFuncSetAttribute(flash_h_kernel,
                         cudaFuncAttributeMaxDynamicSharedMemorySize,
                         FLASH_SMEM_BYTES);

    // 0) Pre-round inputs to fp16 + rope table
    {
        int n2;
        n2 = (MROWS * CC) / 2;
        f2h_kernel<<<(n2 + 255) / 256, 256>>>((const float2*)x, (__half2*)xh, n2);
        n2 = (NQKV * CC) / 2;
        f2h_kernel<<<(n2 + 255) / 256, 256>>>((const float2*)w_att, (__half2*)wah, n2);
        n2 = (CC * CC) / 2;
        f2h_kernel<<<(n2 + 255) / 256, 256>>>((const float2*)w_proj, (__half2*)wph, n2);
        rope_table_kernel<<<(TT * 64 + 255) / 256, 256>>>(rope);
    }

    // 1) QKV projection + fused RoPE -> fp16 qkv
    gemm_h_kernel<<<dim3(NQKV / 128, MROWS / 128), 256, GEMM_SMEM_BYTES>>>(
        xh, wah, b_att, qkvh, rope, 1, MROWS, NQKV, CC);

    // 2) Causal flash attention -> yh [B,T,C] fp16
    flash_h_kernel<<<dim3(TT / 64, BB * NHH), 256, FLASH_SMEM_BYTES>>>(qkvh, yh);

    // 3) Output projection: out = y @ w_proj^T + b_proj (fp32 out)
    gemm_h_kernel<<<dim3(CC / 128, MROWS / 128), 256, GEMM_SMEM_BYTES>>>(
        yh, wph, b_proj, out, rope, 0, MROWS, CC, CC);
}

// round 15
// speedup vs baseline: 1.0245x; 1.0245x over previous
#include <cuda_runtime.h>
#include <cuda_fp16.h>
#include <math.h>
#include <stdint.h>

// Problem constants
#define BB     2
#define TT     2048
#define CC     2048
#define NHH    16
#define HDD    128
#define NQKV   6144          // 3*C
#define MROWS  4096          // B*T

// Scratch (device globals; no allocation allowed)
__device__ __half g_qkvh[(size_t)MROWS * NQKV];     // 48 MB (q,k roped; v raw)
__device__ __half g_yh[(size_t)MROWS * CC];         // 16 MB
__device__ __half g_xh[(size_t)MROWS * CC];         // 16 MB
__device__ __half g_wah[(size_t)NQKV * CC];         // 24 MB
__device__ __half g_wph[(size_t)CC * CC];           // 8 MB
__device__ float2 g_rope[TT * 64];                  // cos/sin table [t][i]

#define NEG_INF (__int_as_float(0xff800000))

// mma.sync m16n8k16 fp16 -> fp32 acc (in-place)
#define MMA_F16(d, a, b) \
    asm volatile("mma.sync.aligned.m16n8k16.row.col.f32.f16.f16.f32 " \
        "{%0,%1,%2,%3}, {%4,%5,%6,%7}, {%8,%9}, {%0,%1,%2,%3};" \
        : "+f"((d)[0]), "+f"((d)[1]), "+f"((d)[2]), "+f"((d)[3]) \
        : "r"((a)[0]), "r"((a)[1]), "r"((a)[2]), "r"((a)[3]), \
          "r"((b)[0]), "r"((b)[1]))

// ldmatrix x4 (non-transposed)
#define LDSM_X4(r0, r1, r2, r3, addr) \
    asm volatile("ldmatrix.sync.aligned.m8n8.x4.shared.b16 {%0,%1,%2,%3}, [%4];" \
        : "=r"(r0), "=r"(r1), "=r"(r2), "=r"(r3) : "r"(addr))

// ldmatrix x4 transposed (for V in [token][d] layout -> B fragments)
#define LDSM_X4_T(r0, r1, r2, r3, addr) \
    asm volatile("ldmatrix.sync.aligned.m8n8.x4.trans.shared.b16 {%0,%1,%2,%3}, [%4];" \
        : "=r"(r0), "=r"(r1), "=r"(r2), "=r"(r3) : "r"(addr))

__device__ __forceinline__ void cp_async16(uint32_t saddr, const void* gptr) {
    asm volatile("cp.async.cg.shared.global [%0], [%1], 16;"
                 :: "r"(saddr), "l"(gptr));
}
#define CP_COMMIT() asm volatile("cp.async.commit_group;" ::: "memory")
#define CP_WAIT(n)  asm volatile("cp.async.wait_group %0;" :: "n"(n) : "memory")

__device__ __forceinline__ uint32_t smem_u32(const void* p) {
    uint32_t a;
    asm("{ .reg .u64 t; cvta.to.shared.u64 t, %1; cvt.u32.u64 %0, t; }"
        : "=r"(a) : "l"(p));
    return a;
}

__device__ __forceinline__ uint32_t pack_h2(float lo, float hi) {
    __half2 h = __floats2half2_rn(lo, hi);
    return *(uint32_t*)&h;
}

// ---------------------------------------------------------------------------
// Fused pre-pass: fp32->fp16 rounding for x, w_att, w_proj + RoPE table.
// ---------------------------------------------------------------------------
#define NX2  (MROWS * CC / 2)          // 4,194,304
#define NWA2 (NQKV * CC / 2)           // 6,291,456
#define NWP2 (CC * CC / 2)             // 2,097,152
#define NRP  (TT * 64)                 // 131,072
#define PREP_TOTAL (NX2 + NWA2 + NWP2 + NRP)

__global__ void prep_kernel(const float2* __restrict__ x,
                            const float2* __restrict__ wa,
                            const float2* __restrict__ wp,
                            __half2* __restrict__ xh,
                            __half2* __restrict__ wah,
                            __half2* __restrict__ wph,
                            float2* __restrict__ rope)
{
    int i = blockIdx.x * blockDim.x + threadIdx.x;
    if (i < NX2) {
        float2 v = x[i];
        xh[i] = __floats2half2_rn(v.x, v.y);
        return;
    }
    i -= NX2;
    if (i < NWA2) {
        float2 v = wa[i];
        wah[i] = __floats2half2_rn(v.x, v.y);
        return;
    }
    i -= NWA2;
    if (i < NWP2) {
        float2 v = wp[i];
        wph[i] = __floats2half2_rn(v.x, v.y);
        return;
    }
    i -= NWP2;
    if (i < NRP) {
        int tpos = i >> 6;
        int ii   = i & 63;
        float theta = 1.0f / powf(10000.0f, (float)ii / 64.0f);
        float ang   = (float)tpos * theta;
        float2 cs;
        cs.x = cosf(ang);
        cs.y = sinf(ang);
        rope[i] = cs;
    }
}

// ---------------------------------------------------------------------------
// FP16 tensor-core GEMM, cp.async 3-stage, CTA 128x128, warp 32x64, BK=64.
// Fragment loads via ldmatrix.x4. ONE barrier per K-step.
// ---------------------------------------------------------------------------
#define PITCH2 36                         // u32 per row (32 data + 4 pad)
#define TILE2_U32 (128 * PITCH2)
#define STAGE2_U32 (2 * TILE2_U32)
#define NSTAGE 3
#define GEMM_SMEM_BYTES (NSTAGE * STAGE2_U32 * 4)   // 110592

__global__ void __launch_bounds__(256, 2) gemm_h_kernel(
    const __half* __restrict__ A, const __half* __restrict__ W,
    const float* __restrict__ bias, void* __restrict__ outv,
    const float2* __restrict__ rope, int qkv_mode,
    int M, int N, int K)
{
    extern __shared__ __align__(16) uint32_t gsm[];
    const uint32_t sbase = smem_u32(gsm);

    const int t = threadIdx.x, lane = t & 31, wid = t >> 5;
    const int wm = wid & 3, wn = wid >> 2;
    const int g = lane >> 2, c = lane & 3;
    const int m0 = blockIdx.y * 128, n0 = blockIdx.x * 128;

    const int quad   = lane >> 3;
    const int lrow_a = (lane & 7) + ((quad & 1) << 3);
    const int kseg_a = (quad >> 1) << 2;
    const int lrow_b = (lane & 7) + ((quad >> 1) << 3);
    const int kseg_b = (quad & 1) << 2;

    const int lrow = t >> 3;             // loader row 0..31
    const int lch  = t & 7;              // loader 16B chunk

    const __half* Ab = A + (size_t)m0 * K;
    const __half* Wb = W + (size_t)n0 * K;

    float acc[2][8][4];
#pragma unroll
    for (int i = 0; i < 2; i++)
#pragma unroll
        for (int j = 0; j < 8; j++)
#pragma unroll
            for (int r = 0; r < 4; r++) acc[i][j][r] = 0.f;

    const int nsteps = K >> 6;           // BK = 64 halves

    auto issue_stage = [&](int s, int kk) {
        const uint32_t sA = sbase + (uint32_t)(s * STAGE2_U32) * 4;
        const uint32_t sB = sA + TILE2_U32 * 4;
        const int kof = kk * 64 + lch * 8;
#pragma unroll
        for (int i = 0; i < 4; i++) {
            const int row = lrow + i * 32;
            cp_async16(sA + (row * PITCH2 + lch * 4) * 4, Ab + (size_t)row * K + kof);
            cp_async16(sB + (row * PITCH2 + lch * 4) * 4, Wb + (size_t)row * K + kof);
        }
        CP_COMMIT();
    };

    issue_stage(0, 0);
    issue_stage(1, 1);

    for (int j = 0; j < nsteps; j++) {
        const int cur = j % NSTAGE;
        CP_WAIT(1);
        __syncthreads();    // stage j visible AND all warps done with buffer (j+2)%3
        if (j + 2 < nsteps) issue_stage((j + 2) % NSTAGE, j + 2);

        const uint32_t sAb = sbase + (uint32_t)(cur * STAGE2_U32) * 4;
        const uint32_t sBb = sAb + TILE2_U32 * 4;
#pragma unroll
        for (int ks = 0; ks < 4; ks++) {          // 4 x k16
            const int kc = ks * 8;
            uint32_t a[2][4];
#pragma unroll
            for (int mt = 0; mt < 2; mt++) {
                const uint32_t ad = sAb +
                    (uint32_t)(((wm * 32 + mt * 16 + lrow_a) * PITCH2) + kc + kseg_a) * 4;
                LDSM_X4(a[mt][0], a[mt][1], a[mt][2], a[mt][3], ad);
            }
            uint32_t bfr[8][2];
#pragma unroll
            for (int p = 0; p < 4; p++) {
                const uint32_t bd = sBb +
                    (uint32_t)(((wn * 64 + p * 16 + lrow_b) * PITCH2) + kc + kseg_b) * 4;
                LDSM_X4(bfr[2 * p][0], bfr[2 * p][1],
                        bfr[2 * p + 1][0], bfr[2 * p + 1][1], bd);
            }
#pragma unroll
            for (int mt = 0; mt < 2; mt++)
#pragma unroll
                for (int nf = 0; nf < 8; nf++)
                    MMA_F16(acc[mt][nf], a[mt], bfr[nf]);
        }
    }

    // epilogue
#pragma unroll
    for (int mt = 0; mt < 2; mt++) {
        const int r0 = m0 + wm * 32 + mt * 16 + g;
        const int tp0 = r0 & (TT - 1);
        const int tp1 = (r0 + 8) & (TT - 1);
#pragma unroll
        for (int nf = 0; nf < 8; nf++) {
            const int col = n0 + wn * 64 + nf * 8 + c * 2;
            const float b0v = bias[col], b1v = bias[col + 1];
            float v00 = acc[mt][nf][0] + b0v;
            float v01 = acc[mt][nf][1] + b1v;
            float v10 = acc[mt][nf][2] + b0v;
            float v11 = acc[mt][nf][3] + b1v;
            if (qkv_mode) {
                if (col < 2 * CC) {
                    const int i = (col & (HDD - 1)) >> 1;
                    const float2 cs0 = rope[tp0 * 64 + i];
                    const float2 cs1 = rope[tp1 * 64 + i];
                    float e0 = v00 * cs0.x - v01 * cs0.y;
                    float o0 = v00 * cs0.y + v01 * cs0.x;
                    float e1 = v10 * cs1.x - v11 * cs1.y;
                    float o1 = v10 * cs1.y + v11 * cs1.x;
                    v00 = e0; v01 = o0; v10 = e1; v11 = o1;
                }
                __half* outh = (__half*)outv;
                *(uint32_t*)(outh + (size_t)r0 * N + col)       = pack_h2(v00, v01);
                *(uint32_t*)(outh + (size_t)(r0 + 8) * N + col) = pack_h2(v10, v11);
            } else {
                float* outf = (float*)outv;
                float* o0p = outf + (size_t)r0 * N + col;
                float* o1p = outf + (size_t)(r0 + 8) * N + col;
                o0p[0] = v00; o0p[1] = v01;
                o1p[0] = v10; o1p[1] = v11;
            }
        }
    }
}

// ---------------------------------------------------------------------------
// Flash attention: Q-tile 64, 256 threads, 2 CTAs/SM.
// K double-buffered (prefetch next tile during softmax/PV).
// V in natural [token][d] layout; PV B-frags via ldmatrix.trans.
// ---------------------------------------------------------------------------
#define FQP2 68    // u32 pitch for Q/K/V rows (64 data + 4)
#define FVP2 36    // u32 pitch for P rows (32 data + 4)
#define FL_T_U32  (64 * FQP2)     // 4352 (one 64x128 half tile)
#define FL_S_U32  (64 * FVP2)     // 2304
#define FL_STATS  (6 * 64)
#define FLASH_SMEM_U32 (4 * FL_T_U32 + FL_S_U32 + FL_STATS)   // Q,K0,K1,V + S + stats
#define FLASH_SMEM_BYTES (FLASH_SMEM_U32 * 4)    // ~80.4 KB

__global__ void __launch_bounds__(256, 2) flash_h_kernel(
    const __half* __restrict__ qkvh, __half* __restrict__ y)
{
    extern __shared__ uint32_t fsm[];
    uint32_t* Ssu = fsm + 4 * FL_T_U32;
    float* pmax = (float*)(Ssu + FL_S_U32);
    float* psum = pmax + 2 * 64;
    float* mrow = psum + 2 * 64;
    float* lrow = mrow + 64;

    const uint32_t Qsb = smem_u32(fsm);
    const uint32_t K0b = Qsb + FL_T_U32 * 4;
    const uint32_t K1b = K0b + FL_T_U32 * 4;
    const uint32_t Vb  = K1b + FL_T_U32 * 4;
    const uint32_t Ssb = Vb + FL_T_U32 * 4;

    const int bh = blockIdx.y, b = bh >> 4, h = bh & 15;
    const int qt = gridDim.x - 1 - blockIdx.x;    // heavy tiles first
    const int q0 = qt * 64;
    const int t = threadIdx.x, lane = t & 31, wid = t >> 5;
    const int wm = wid & 3, wn = wid >> 2;
    const int g = lane >> 2, c = lane & 3;
    const float scale = 0.08838834764831845f;   // 1/sqrt(128)

    const int quad   = lane >> 3;
    const int lrow_a = (lane & 7) + ((quad & 1) << 3);
    const int kseg_a = (quad >> 1) << 2;
    const int lrow_b = (lane & 7) + ((quad >> 1) << 3);
    const int kseg_b = (quad & 1) << 2;

    // trans-ldmatrix lane mapping for V [token][d]
    const int vrow = lane & 15;
    const int vseg = (lane >> 4) << 2;

    const __half* Qg = qkvh + ((size_t)(b * TT + q0)) * NQKV + h * HDD;
    const __half* Kbase = qkvh + (size_t)b * TT * NQKV + CC + h * HDD;
    const __half* Vbase = Kbase + CC;

    // load Q tile + K(0) tile via cp.async
#pragma unroll
    for (int i = 0; i < 4; i++) {
        const int idx = t + i * 256;
        const int rr = idx >> 4, cc = idx & 15;
        cp_async16(Qsb + (rr * FQP2 + cc * 4) * 4,
                   Qg + (size_t)rr * NQKV + cc * 8);
    }
    CP_COMMIT();
#pragma unroll
    for (int i = 0; i < 4; i++) {
        const int idx = t + i * 256;
        const int rr = idx >> 4, cc = idx & 15;
        cp_async16(K0b + (rr * FQP2 + cc * 4) * 4,
                   Kbase + (size_t)rr * NQKV + cc * 8);
    }
    CP_COMMIT();
    if (t < 64) { mrow[t] = NEG_INF; lrow[t] = 0.f; }

    const int r0 = wm * 16 + g;
    const int qg0 = q0 + r0, qg1 = q0 + r0 + 8;

    float acc_o[8][4];
#pragma unroll
    for (int j = 0; j < 8; j++)
#pragma unroll
        for (int r = 0; r < 4; r++) acc_o[j][r] = 0.f;

    for (int kt = 0; kt <= qt; kt++) {
        const int k0 = kt * 64;
        const uint32_t Kb = (kt & 1) ? K1b : K0b;

        __syncthreads();               // prev iter done with V/Ss; K(kt) buffer safe
        CP_WAIT(0);                    // K(kt) (and Q on iter 0) arrived
        __syncthreads();               // visible to all warps

        // S = Q K^T  (8 x k16 chunks over d=128)
        float acc_s[4][4];
#pragma unroll
        for (int j = 0; j < 4; j++)
#pragma unroll
            for (int r = 0; r < 4; r++) acc_s[j][r] = 0.f;
#pragma unroll
        for (int ks = 0; ks < 8; ks++) {
            const int kc = ks * 8;
            uint32_t a[4];
            {
                const uint32_t ad = Qsb +
                    (uint32_t)(((wm * 16 + lrow_a) * FQP2) + kc + kseg_a) * 4;
                LDSM_X4(a[0], a[1], a[2], a[3], ad);
            }
            uint32_t bf[4][2];
#pragma unroll
            for (int p = 0; p < 2; p++) {
                const uint32_t bd = Kb +
                    (uint32_t)(((wn * 32 + p * 16 + lrow_b) * FQP2) + kc + kseg_b) * 4;
                LDSM_X4(bf[2 * p][0], bf[2 * p][1],
                        bf[2 * p + 1][0], bf[2 * p + 1][1], bd);
            }
#pragma unroll
            for (int nf = 0; nf < 4; nf++)
                MMA_F16(acc_s[nf], a, bf[nf]);
        }

        // scale + causal mask
#pragma unroll
        for (int nf = 0; nf < 4; nf++) {
            const int kg0 = k0 + wn * 32 + nf * 8 + c * 2;
            acc_s[nf][0] = (kg0     <= qg0) ? acc_s[nf][0] * scale : NEG_INF;
            acc_s[nf][1] = (kg0 + 1 <= qg0) ? acc_s[nf][1] * scale : NEG_INF;
            acc_s[nf][2] = (kg0     <= qg1) ? acc_s[nf][2] * scale : NEG_INF;
            acc_s[nf][3] = (kg0 + 1 <= qg1) ? acc_s[nf][3] * scale : NEG_INF;
        }

        // warp-level row max
        float mx0 = NEG_INF, mx1 = NEG_INF;
#pragma unroll
        for (int nf = 0; nf < 4; nf++) {
            mx0 = fmaxf(mx0, fmaxf(acc_s[nf][0], acc_s[nf][1]));
            mx1 = fmaxf(mx1, fmaxf(acc_s[nf][2], acc_s[nf][3]));
        }
        mx0 = fmaxf(mx0, __shfl_xor_sync(0xffffffffu, mx0, 1));
        mx0 = fmaxf(mx0, __shfl_xor_sync(0xffffffffu, mx0, 2));
        mx1 = fmaxf(mx1, __shfl_xor_sync(0xffffffffu, mx1, 1));
        mx1 = fmaxf(mx1, __shfl_xor_sync(0xffffffffu, mx1, 2));
        if (c == 0) {
            pmax[wn * 64 + r0]     = mx0;
            pmax[wn * 64 + r0 + 8] = mx1;
        }
        __syncthreads();               // pmax ready; V buffer free (prev PV done)

        // issue V(kt) load, then prefetch K(kt+1) into the other K buffer
        {
            const __half* Vg = Vbase + (size_t)k0 * NQKV;
#pragma unroll
            for (int i = 0; i < 4; i++) {
                const int idx = t + i * 256;
                const int rr = idx >> 4, cc = idx & 15;
                cp_async16(Vb + (rr * FQP2 + cc * 4) * 4,
                           Vg + (size_t)rr * NQKV + cc * 8);
            }
            CP_COMMIT();
        }
        if (kt < qt) {
            const __half* Kn = Kbase + (size_t)(k0 + 64) * NQKV;
            const uint32_t Ko = (kt & 1) ? K0b : K1b;
#pragma unroll
            for (int i = 0; i < 4; i++) {
                const int idx = t + i * 256;
                const int rr = idx >> 4, cc = idx & 15;
                cp_async16(Ko + (rr * FQP2 + cc * 4) * 4,
                           Kn + (size_t)rr * NQKV + cc * 8);
            }
            CP_COMMIT();
        }

        // combine max, exp, partial sums, write P (fp16)
        const float oldm0 = mrow[r0], oldm1 = mrow[r0 + 8];
        const float mnew0 = fmaxf(oldm0, fmaxf(pmax[r0], pmax[64 + r0]));
        const float mnew1 = fmaxf(oldm1, fmaxf(pmax[r0 + 8], pmax[64 + r0 + 8]));
        const float f0 = __expf(oldm0 - mnew0);
        const float f1 = __expf(oldm1 - mnew1);

        float s0 = 0.f, s1 = 0.f;
#pragma unroll
        for (int nf = 0; nf < 4; nf++) {
            const int cu = wn * 16 + nf * 4 + c;
            float p00 = __expf(acc_s[nf][0] - mnew0);
            float p01 = __expf(acc_s[nf][1] - mnew0);
            float p10 = __expf(acc_s[nf][2] - mnew1);
            float p11 = __expf(acc_s[nf][3] - mnew1);
            s0 += p00 + p01;
            s1 += p10 + p11;
            Ssu[r0 * FVP2 + cu]       = pack_h2(p00, p01);
            Ssu[(r0 + 8) * FVP2 + cu] = pack_h2(p10, p11);
        }
        s0 += __shfl_xor_sync(0xffffffffu, s0, 1);
        s0 += __shfl_xor_sync(0xffffffffu, s0, 2);
        s1 += __shfl_xor_sync(0xffffffffu, s1, 1);
        s1 += __shfl_xor_sync(0xffffffffu, s1, 2);
        if (c == 0) {
            psum[wn * 64 + r0]     = s0;
            psum[wn * 64 + r0 + 8] = s1;
        }
        if (kt < qt) { CP_WAIT(1); }   // V done; K(kt+1) may still fly
        else         { CP_WAIT(0); }
        __syncthreads();               // V + P + psum visible

        if (wn == 0 && c == 0) {
            lrow[r0]     = lrow[r0]     * f0 + psum[r0]     + psum[64 + r0];
            lrow[r0 + 8] = lrow[r0 + 8] * f1 + psum[r0 + 8] + psum[64 + r0 + 8];
            mrow[r0]     = mnew0;
            mrow[r0 + 8] = mnew1;
        }
#pragma unroll
        for (int nf = 0; nf < 8; nf++) {
            acc_o[nf][0] *= f0; acc_o[nf][1] *= f0;
            acc_o[nf][2] *= f1; acc_o[nf][3] *= f1;
        }

        // O += P V   (4 x k16 token-chunks; V B-frags via ldmatrix.trans)
#pragma unroll
        for (int ks = 0; ks < 4; ks++) {
            const int kc = ks * 8;
            uint32_t p[4];
            {
                const uint32_t pd = Ssb +
                    (uint32_t)(((wm * 16 + lrow_a) * FVP2) + kc + kseg_a) * 4;
                LDSM_X4(p[0], p[1], p[2], p[3], pd);
            }
            uint32_t vf[8][2];
#pragma unroll
            for (int db = 0; db < 4; db++) {
                const uint32_t vd = Vb +
                    (uint32_t)(((ks * 16 + vrow) * FQP2) + wn * 32 + db * 8 + vseg) * 4;
                LDSM_X4_T(vf[2 * db][0], vf[2 * db][1],
                          vf[2 * db + 1][0], vf[2 * db + 1][1], vd);
            }
#pragma unroll
            for (int nf = 0; nf < 8; nf++)
                MMA_F16(acc_o[nf], p, vf[nf]);
        }
    }

    __syncthreads();

    // epilogue: divide by l, store fp16 y
    {
        const float li0 = 1.0f / lrow[r0];
        const float li1 = 1.0f / lrow[r0 + 8];
        __half* y0 = y + ((size_t)(b * TT + q0 + r0)) * CC + h * HDD;
        __half* y1 = y + ((size_t)(b * TT + q0 + r0 + 8)) * CC + h * HDD;
#pragma unroll
        for (int nf = 0; nf < 8; nf++) {
            const int col = wn * 64 + nf * 8 + c * 2;
            *(uint32_t*)(y0 + col) = pack_h2(acc_o[nf][0] * li0, acc_o[nf][1] * li0);
            *(uint32_t*)(y1 + col) = pack_h2(acc_o[nf][2] * li1, acc_o[nf][3] * li1);
        }
    }
}

// ---------------------------------------------------------------------------
// Launch
// ---------------------------------------------------------------------------
extern "C" void kernel_launch(void* const* d_in, const int* in_sizes, int n_in,
                              void* d_out, int out_size)
{
    const float* x      = (const float*)d_in[0];   // [2,2048,2048]
    const float* w_att  = (const float*)d_in[1];   // [6144,2048]
    const float* b_att  = (const float*)d_in[2];   // [6144]
    const float* w_proj = (const float*)d_in[3];   // [2048,2048]
    const float* b_proj = (const float*)d_in[4];   // [2048]
    float* out = (float*)d_out;                    // [2,2048,2048]

    __half *qkvh, *yh, *xh, *wah, *wph;
    float2* rope;
    cudaGetSymbolAddress((void**)&qkvh, g_qkvh);
    cudaGetSymbolAddress((void**)&yh,   g_yh);
    cudaGetSymbolAddress((void**)&xh,   g_xh);
    cudaGetSymbolAddress((void**)&wah,  g_wah);
    cudaGetSymbolAddress((void**)&wph,  g_wph);
    cudaGetSymbolAddress((void**)&rope, g_rope);

    cudaFuncSetAttribute(gemm_h_kernel,
                         cudaFuncAttributeMaxDynamicSharedMemorySize,
                         GEMM_SMEM_BYTES);
    cudaFuncSetAttribute(flash_h_kernel,
                         cudaFuncAttributeMaxDynamicSharedMemorySize,
                         FLASH_SMEM_BYTES);

    // 0) Fused pre-pass: fp16 rounding of x/w_att/w_proj + rope table
    prep_kernel<<<(PREP_TOTAL + 255) / 256, 256>>>(
        (const float2*)x, (const float2*)w_att, (const float2*)w_proj,
        (__half2*)xh, (__half2*)wah, (__half2*)wph, rope);

    // 1) QKV projection + fused RoPE -> fp16 qkv
    gemm_h_kernel<<<dim3(NQKV / 128, MROWS / 128), 256, GEMM_SMEM_BYTES>>>(
        xh, wah, b_att, qkvh, rope, 1, MROWS, NQKV, CC);

    // 2) Causal flash attention -> yh [B,T,C] fp16
    flash_h_kernel<<<dim3(TT / 64, BB * NHH), 256, FLASH_SMEM_BYTES>>>(qkvh, yh);

    // 3) Output projection: out = y @ w_proj^T + b_proj (fp32 out)
    gemm_h_kernel<<<dim3(CC / 128, MROWS / 128), 256, GEMM_SMEM_BYTES>>>(
        yh, wph, b_proj, out, rope, 0, MROWS, CC, CC);
}

// round 16
// speedup vs baseline: 1.0259x; 1.0014x over previous
#include <cuda_runtime.h>
#include <cuda_fp16.h>
#include <math.h>
#include <stdint.h>

// Problem constants
#define BB     2
#define TT     2048
#define CC     2048
#define NHH    16
#define HDD    128
#define NQKV   6144          // 3*C
#define MROWS  4096          // B*T

// Scratch (device globals; no allocation allowed)
__device__ __half g_qkvh[(size_t)MROWS * NQKV];     // 48 MB (q,k roped; v raw)
__device__ __half g_yh[(size_t)MROWS * CC];         // 16 MB
__device__ __half g_xh[(size_t)MROWS * CC];         // 16 MB
__device__ __half g_wah[(size_t)NQKV * CC];         // 24 MB
__device__ __half g_wph[(size_t)CC * CC];           // 8 MB
__device__ float2 g_rope[TT * 64];                  // cos/sin table [t][i]

#define NEG_INF (__int_as_float(0xff800000))

// mma.sync m16n8k16 fp16 -> fp32 acc (in-place)
#define MMA_F16(d, a, b) \
    asm volatile("mma.sync.aligned.m16n8k16.row.col.f32.f16.f16.f32 " \
        "{%0,%1,%2,%3}, {%4,%5,%6,%7}, {%8,%9}, {%0,%1,%2,%3};" \
        : "+f"((d)[0]), "+f"((d)[1]), "+f"((d)[2]), "+f"((d)[3]) \
        : "r"((a)[0]), "r"((a)[1]), "r"((a)[2]), "r"((a)[3]), \
          "r"((b)[0]), "r"((b)[1]))

// ldmatrix x4 (non-transposed)
#define LDSM_X4(r0, r1, r2, r3, addr) \
    asm volatile("ldmatrix.sync.aligned.m8n8.x4.shared.b16 {%0,%1,%2,%3}, [%4];" \
        : "=r"(r0), "=r"(r1), "=r"(r2), "=r"(r3) : "r"(addr))

// ldmatrix x4 transposed (for V in [token][d] layout -> B fragments)
#define LDSM_X4_T(r0, r1, r2, r3, addr) \
    asm volatile("ldmatrix.sync.aligned.m8n8.x4.trans.shared.b16 {%0,%1,%2,%3}, [%4];" \
        : "=r"(r0), "=r"(r1), "=r"(r2), "=r"(r3) : "r"(addr))

__device__ __forceinline__ void cp_async16(uint32_t saddr, const void* gptr) {
    asm volatile("cp.async.cg.shared.global [%0], [%1], 16;"
                 :: "r"(saddr), "l"(gptr));
}
#define CP_COMMIT() asm volatile("cp.async.commit_group;" ::: "memory")
#define CP_WAIT(n)  asm volatile("cp.async.wait_group %0;" :: "n"(n) : "memory")

__device__ __forceinline__ uint32_t smem_u32(const void* p) {
    uint32_t a;
    asm("{ .reg .u64 t; cvta.to.shared.u64 t, %1; cvt.u32.u64 %0, t; }"
        : "=r"(a) : "l"(p));
    return a;
}

__device__ __forceinline__ uint32_t pack_h2(float lo, float hi) {
    __half2 h = __floats2half2_rn(lo, hi);
    return *(uint32_t*)&h;
}

// ---------------------------------------------------------------------------
// Fused pre-pass: fp32->fp16 rounding for x, w_att, w_proj + RoPE table.
// ---------------------------------------------------------------------------
#define NX2  (MROWS * CC / 2)
#define NWA2 (NQKV * CC / 2)
#define NWP2 (CC * CC / 2)
#define NRP  (TT * 64)
#define PREP_TOTAL (NX2 + NWA2 + NWP2 + NRP)

__global__ void prep_kernel(const float2* __restrict__ x,
                            const float2* __restrict__ wa,
                            const float2* __restrict__ wp,
                            __half2* __restrict__ xh,
                            __half2* __restrict__ wah,
                            __half2* __restrict__ wph,
                            float2* __restrict__ rope)
{
    int i = blockIdx.x * blockDim.x + threadIdx.x;
    if (i < NX2) {
        float2 v = x[i];
        xh[i] = __floats2half2_rn(v.x, v.y);
        return;
    }
    i -= NX2;
    if (i < NWA2) {
        float2 v = wa[i];
        wah[i] = __floats2half2_rn(v.x, v.y);
        return;
    }
    i -= NWA2;
    if (i < NWP2) {
        float2 v = wp[i];
        wph[i] = __floats2half2_rn(v.x, v.y);
        return;
    }
    i -= NWP2;
    if (i < NRP) {
        int tpos = i >> 6;
        int ii   = i & 63;
        float theta = 1.0f / powf(10000.0f, (float)ii / 64.0f);
        float ang   = (float)tpos * theta;
        float2 cs;
        cs.x = cosf(ang);
        cs.y = sinf(ang);
        rope[i] = cs;
    }
}

// ---------------------------------------------------------------------------
// FP16 tensor-core GEMM, cp.async 3-stage, CTA 128x128, warp 32x64, BK=64.
// ---------------------------------------------------------------------------
#define PITCH2 36                         // u32 per row (32 data + 4 pad)
#define TILE2_U32 (128 * PITCH2)
#define STAGE2_U32 (2 * TILE2_U32)
#define NSTAGE 3
#define GEMM_SMEM_BYTES (NSTAGE * STAGE2_U32 * 4)   // 110592

__global__ void __launch_bounds__(256, 2) gemm_h_kernel(
    const __half* __restrict__ A, const __half* __restrict__ W,
    const float* __restrict__ bias, void* __restrict__ outv,
    const float2* __restrict__ rope, int qkv_mode,
    int M, int N, int K)
{
    extern __shared__ __align__(16) uint32_t gsm[];
    const uint32_t sbase = smem_u32(gsm);

    const int t = threadIdx.x, lane = t & 31, wid = t >> 5;
    const int wm = wid & 3, wn = wid >> 2;
    const int g = lane >> 2, c = lane & 3;
    const int m0 = blockIdx.y * 128, n0 = blockIdx.x * 128;

    const int quad   = lane >> 3;
    const int lrow_a = (lane & 7) + ((quad & 1) << 3);
    const int kseg_a = (quad >> 1) << 2;
    const int lrow_b = (lane & 7) + ((quad >> 1) << 3);
    const int kseg_b = (quad & 1) << 2;

    const int lrow = t >> 3;             // loader row 0..31
    const int lch  = t & 7;              // loader 16B chunk

    const __half* Ab = A + (size_t)m0 * K;
    const __half* Wb = W + (size_t)n0 * K;

    float acc[2][8][4];
#pragma unroll
    for (int i = 0; i < 2; i++)
#pragma unroll
        for (int j = 0; j < 8; j++)
#pragma unroll
            for (int r = 0; r < 4; r++) acc[i][j][r] = 0.f;

    const int nsteps = K >> 6;           // BK = 64 halves

    auto issue_stage = [&](int s, int kk) {
        const uint32_t sA = sbase + (uint32_t)(s * STAGE2_U32) * 4;
        const uint32_t sB = sA + TILE2_U32 * 4;
        const int kof = kk * 64 + lch * 8;
#pragma unroll
        for (int i = 0; i < 4; i++) {
            const int row = lrow + i * 32;
            cp_async16(sA + (row * PITCH2 + lch * 4) * 4, Ab + (size_t)row * K + kof);
            cp_async16(sB + (row * PITCH2 + lch * 4) * 4, Wb + (size_t)row * K + kof);
        }
        CP_COMMIT();
    };

    issue_stage(0, 0);
    issue_stage(1, 1);

    for (int j = 0; j < nsteps; j++) {
        const int cur = j % NSTAGE;
        CP_WAIT(1);
        __syncthreads();    // stage j visible AND all warps done with buffer (j+2)%3
        if (j + 2 < nsteps) issue_stage((j + 2) % NSTAGE, j + 2);

        const uint32_t sAb = sbase + (uint32_t)(cur * STAGE2_U32) * 4;
        const uint32_t sBb = sAb + TILE2_U32 * 4;
#pragma unroll
        for (int ks = 0; ks < 4; ks++) {          // 4 x k16
            const int kc = ks * 8;
            uint32_t a[2][4];
#pragma unroll
            for (int mt = 0; mt < 2; mt++) {
                const uint32_t ad = sAb +
                    (uint32_t)(((wm * 32 + mt * 16 + lrow_a) * PITCH2) + kc + kseg_a) * 4;
                LDSM_X4(a[mt][0], a[mt][1], a[mt][2], a[mt][3], ad);
            }
            uint32_t bfr[8][2];
#pragma unroll
            for (int p = 0; p < 4; p++) {
                const uint32_t bd = sBb +
                    (uint32_t)(((wn * 64 + p * 16 + lrow_b) * PITCH2) + kc + kseg_b) * 4;
                LDSM_X4(bfr[2 * p][0], bfr[2 * p][1],
                        bfr[2 * p + 1][0], bfr[2 * p + 1][1], bd);
            }
#pragma unroll
            for (int mt = 0; mt < 2; mt++)
#pragma unroll
                for (int nf = 0; nf < 8; nf++)
                    MMA_F16(acc[mt][nf], a[mt], bfr[nf]);
        }
    }

    // epilogue
#pragma unroll
    for (int mt = 0; mt < 2; mt++) {
        const int r0 = m0 + wm * 32 + mt * 16 + g;
        const int tp0 = r0 & (TT - 1);
        const int tp1 = (r0 + 8) & (TT - 1);
#pragma unroll
        for (int nf = 0; nf < 8; nf++) {
            const int col = n0 + wn * 64 + nf * 8 + c * 2;
            const float b0v = bias[col], b1v = bias[col + 1];
            float v00 = acc[mt][nf][0] + b0v;
            float v01 = acc[mt][nf][1] + b1v;
            float v10 = acc[mt][nf][2] + b0v;
            float v11 = acc[mt][nf][3] + b1v;
            if (qkv_mode) {
                if (col < 2 * CC) {
                    const int i = (col & (HDD - 1)) >> 1;
                    const float2 cs0 = rope[tp0 * 64 + i];
                    const float2 cs1 = rope[tp1 * 64 + i];
                    float e0 = v00 * cs0.x - v01 * cs0.y;
                    float o0 = v00 * cs0.y + v01 * cs0.x;
                    float e1 = v10 * cs1.x - v11 * cs1.y;
                    float o1 = v10 * cs1.y + v11 * cs1.x;
                    v00 = e0; v01 = o0; v10 = e1; v11 = o1;
                }
                __half* outh = (__half*)outv;
                *(uint32_t*)(outh + (size_t)r0 * N + col)       = pack_h2(v00, v01);
                *(uint32_t*)(outh + (size_t)(r0 + 8) * N + col) = pack_h2(v10, v11);
            } else {
                float* outf = (float*)outv;
                float* o0p = outf + (size_t)r0 * N + col;
                float* o1p = outf + (size_t)(r0 + 8) * N + col;
                o0p[0] = v00; o0p[1] = v01;
                o1p[0] = v10; o1p[1] = v11;
            }
        }
    }
}

// ---------------------------------------------------------------------------
// Flash attention: Q-tile 64, 256 threads, 2 CTAs/SM.
// K double-buffered; V natural layout with trans-ldmatrix.
// m/l softmax state register-resident (redundant per-row compute).
// 3 syncs per kv-tile.
// ---------------------------------------------------------------------------
#define FQP2 68    // u32 pitch for Q/K/V rows (64 data + 4)
#define FVP2 36    // u32 pitch for P rows (32 data + 4)
#define FL_T_U32  (64 * FQP2)     // 4352 (one 64x128 half tile)
#define FL_S_U32  (64 * FVP2)     // 2304
#define FL_STATS  (4 * 64)        // pmax[2][64], psum[2][64]
#define FLASH_SMEM_U32 (4 * FL_T_U32 + FL_S_U32 + FL_STATS)   // Q,K0,K1,V + S + stats
#define FLASH_SMEM_BYTES (FLASH_SMEM_U32 * 4)    // ~80 KB

__global__ void __launch_bounds__(256, 2) flash_h_kernel(
    const __half* __restrict__ qkvh, __half* __restrict__ y)
{
    extern __shared__ uint32_t fsm[];
    uint32_t* Ssu = fsm + 4 * FL_T_U32;
    float* pmax = (float*)(Ssu + FL_S_U32);   // [2][64]
    float* psum = pmax + 2 * 64;              // [2][64]

    const uint32_t Qsb = smem_u32(fsm);
    const uint32_t K0b = Qsb + FL_T_U32 * 4;
    const uint32_t K1b = K0b + FL_T_U32 * 4;
    const uint32_t Vb  = K1b + FL_T_U32 * 4;
    const uint32_t Ssb = Vb + FL_T_U32 * 4;

    const int bh = blockIdx.y, b = bh >> 4, h = bh & 15;
    const int qt = gridDim.x - 1 - blockIdx.x;    // heavy tiles first
    const int q0 = qt * 64;
    const int t = threadIdx.x, lane = t & 31, wid = t >> 5;
    const int wm = wid & 3, wn = wid >> 2;
    const int g = lane >> 2, c = lane & 3;
    const float scale = 0.08838834764831845f;   // 1/sqrt(128)

    const int quad   = lane >> 3;
    const int lrow_a = (lane & 7) + ((quad & 1) << 3);
    const int kseg_a = (quad >> 1) << 2;
    const int lrow_b = (lane & 7) + ((quad >> 1) << 3);
    const int kseg_b = (quad & 1) << 2;

    // trans-ldmatrix lane mapping for V [token][d]
    const int vrow = lane & 15;
    const int vseg = (lane >> 4) << 2;

    const __half* Qg = qkvh + ((size_t)(b * TT + q0)) * NQKV + h * HDD;
    const __half* Kbase = qkvh + (size_t)b * TT * NQKV + CC + h * HDD;
    const __half* Vbase = Kbase + CC;

    // load Q tile + K(0) tile via cp.async
#pragma unroll
    for (int i = 0; i < 4; i++) {
        const int idx = t + i * 256;
        const int rr = idx >> 4, cc = idx & 15;
        cp_async16(Qsb + (rr * FQP2 + cc * 4) * 4,
                   Qg + (size_t)rr * NQKV + cc * 8);
    }
    CP_COMMIT();
#pragma unroll
    for (int i = 0; i < 4; i++) {
        const int idx = t + i * 256;
        const int rr = idx >> 4, cc = idx & 15;
        cp_async16(K0b + (rr * FQP2 + cc * 4) * 4,
                   Kbase + (size_t)rr * NQKV + cc * 8);
    }
    CP_COMMIT();

    const int r0 = wm * 16 + g;
    const int qg0 = q0 + r0, qg1 = q0 + r0 + 8;

    // register-resident softmax state (rows r0 and r0+8)
    float m0r = NEG_INF, m1r = NEG_INF;
    float l0r = 0.f, l1r = 0.f;

    float acc_o[8][4];
#pragma unroll
    for (int j = 0; j < 8; j++)
#pragma unroll
        for (int r = 0; r < 4; r++) acc_o[j][r] = 0.f;

    for (int kt = 0; kt <= qt; kt++) {
        const int k0 = kt * 64;
        const uint32_t Kb = (kt & 1) ? K1b : K0b;

        CP_WAIT(0);                    // K(kt) (and Q on iter 0) arrived
        __syncthreads();               // visible to all; prev iter done with V/Ss

        // S = Q K^T  (8 x k16 chunks over d=128)
        float acc_s[4][4];
#pragma unroll
        for (int j = 0; j < 4; j++)
#pragma unroll
            for (int r = 0; r < 4; r++) acc_s[j][r] = 0.f;
#pragma unroll
        for (int ks = 0; ks < 8; ks++) {
            const int kc = ks * 8;
            uint32_t a[4];
            {
                const uint32_t ad = Qsb +
                    (uint32_t)(((wm * 16 + lrow_a) * FQP2) + kc + kseg_a) * 4;
                LDSM_X4(a[0], a[1], a[2], a[3], ad);
            }
            uint32_t bf[4][2];
#pragma unroll
            for (int p = 0; p < 2; p++) {
                const uint32_t bd = Kb +
                    (uint32_t)(((wn * 32 + p * 16 + lrow_b) * FQP2) + kc + kseg_b) * 4;
                LDSM_X4(bf[2 * p][0], bf[2 * p][1],
                        bf[2 * p + 1][0], bf[2 * p + 1][1], bd);
            }
#pragma unroll
            for (int nf = 0; nf < 4; nf++)
                MMA_F16(acc_s[nf], a, bf[nf]);
        }

        // scale + causal mask
#pragma unroll
        for (int nf = 0; nf < 4; nf++) {
            const int kg0 = k0 + wn * 32 + nf * 8 + c * 2;
            acc_s[nf][0] = (kg0     <= qg0) ? acc_s[nf][0] * scale : NEG_INF;
            acc_s[nf][1] = (kg0 + 1 <= qg0) ? acc_s[nf][1] * scale : NEG_INF;
            acc_s[nf][2] = (kg0     <= qg1) ? acc_s[nf][2] * scale : NEG_INF;
            acc_s[nf][3] = (kg0 + 1 <= qg1) ? acc_s[nf][3] * scale : NEG_INF;
        }

        // warp-level row max
        float mx0 = NEG_INF, mx1 = NEG_INF;
#pragma unroll
        for (int nf = 0; nf < 4; nf++) {
            mx0 = fmaxf(mx0, fmaxf(acc_s[nf][0], acc_s[nf][1]));
            mx1 = fmaxf(mx1, fmaxf(acc_s[nf][2], acc_s[nf][3]));
        }
        mx0 = fmaxf(mx0, __shfl_xor_sync(0xffffffffu, mx0, 1));
        mx0 = fmaxf(mx0, __shfl_xor_sync(0xffffffffu, mx0, 2));
        mx1 = fmaxf(mx1, __shfl_xor_sync(0xffffffffu, mx1, 1));
        mx1 = fmaxf(mx1, __shfl_xor_sync(0xffffffffu, mx1, 2));
        if (c == 0) {
            pmax[wn * 64 + r0]     = mx0;
            pmax[wn * 64 + r0 + 8] = mx1;
        }
        __syncthreads();               // pmax ready; V buffer free (prev PV done)

        // issue V(kt) load, then prefetch K(kt+1) into the other K buffer
        {
            const __half* Vg = Vbase + (size_t)k0 * NQKV;
#pragma unroll
            for (int i = 0; i < 4; i++) {
                const int idx = t + i * 256;
                const int rr = idx >> 4, cc = idx & 15;
                cp_async16(Vb + (rr * FQP2 + cc * 4) * 4,
                           Vg + (size_t)rr * NQKV + cc * 8);
            }
            CP_COMMIT();
        }
        if (kt < qt) {
            const __half* Kn = Kbase + (size_t)(k0 + 64) * NQKV;
            const uint32_t Ko = (kt & 1) ? K0b : K1b;
#pragma unroll
            for (int i = 0; i < 4; i++) {
                const int idx = t + i * 256;
                const int rr = idx >> 4, cc = idx & 15;
                cp_async16(Ko + (rr * FQP2 + cc * 4) * 4,
                           Kn + (size_t)rr * NQKV + cc * 8);
            }
            CP_COMMIT();
        }

        // combine max, exp, partial sums, write P (fp16)
        const float mnew0 = fmaxf(m0r, fmaxf(pmax[r0], pmax[64 + r0]));
        const float mnew1 = fmaxf(m1r, fmaxf(pmax[r0 + 8], pmax[64 + r0 + 8]));
        const float f0 = __expf(m0r - mnew0);
        const float f1 = __expf(m1r - mnew1);
        m0r = mnew0;
        m1r = mnew1;

        float s0 = 0.f, s1 = 0.f;
#pragma unroll
        for (int nf = 0; nf < 4; nf++) {
            const int cu = wn * 16 + nf * 4 + c;
            float p00 = __expf(acc_s[nf][0] - mnew0);
            float p01 = __expf(acc_s[nf][1] - mnew0);
            float p10 = __expf(acc_s[nf][2] - mnew1);
            float p11 = __expf(acc_s[nf][3] - mnew1);
            s0 += p00 + p01;
            s1 += p10 + p11;
            Ssu[r0 * FVP2 + cu]       = pack_h2(p00, p01);
            Ssu[(r0 + 8) * FVP2 + cu] = pack_h2(p10, p11);
        }
        s0 += __shfl_xor_sync(0xffffffffu, s0, 1);
        s0 += __shfl_xor_sync(0xffffffffu, s0, 2);
        s1 += __shfl_xor_sync(0xffffffffu, s1, 1);
        s1 += __shfl_xor_sync(0xffffffffu, s1, 2);
        if (c == 0) {
            psum[wn * 64 + r0]     = s0;
            psum[wn * 64 + r0 + 8] = s1;
        }
        if (kt < qt) { CP_WAIT(1); }   // V done; K(kt+1) may still fly
        else         { CP_WAIT(0); }
        __syncthreads();               // V + P + psum visible

        // l update from both warps' partial sums (register-resident)
        l0r = l0r * f0 + psum[r0]     + psum[64 + r0];
        l1r = l1r * f1 + psum[r0 + 8] + psum[64 + r0 + 8];

#pragma unroll
        for (int nf = 0; nf < 8; nf++) {
            acc_o[nf][0] *= f0; acc_o[nf][1] *= f0;
            acc_o[nf][2] *= f1; acc_o[nf][3] *= f1;
        }

        // O += P V   (4 x k16 token-chunks; V B-frags via ldmatrix.trans)
#pragma unroll
        for (int ks = 0; ks < 4; ks++) {
            const int kc = ks * 8;
            uint32_t p[4];
            {
                const uint32_t pd = Ssb +
                    (uint32_t)(((wm * 16 + lrow_a) * FVP2) + kc + kseg_a) * 4;
                LDSM_X4(p[0], p[1], p[2], p[3], pd);
            }
            uint32_t vf[8][2];
#pragma unroll
            for (int db = 0; db < 4; db++) {
                const uint32_t vd = Vb +
                    (uint32_t)(((ks * 16 + vrow) * FQP2) + wn * 32 + db * 8 + vseg) * 4;
                LDSM_X4_T(vf[2 * db][0], vf[2 * db][1],
                          vf[2 * db + 1][0], vf[2 * db + 1][1], vd);
            }
#pragma unroll
            for (int nf = 0; nf < 8; nf++)
                MMA_F16(acc_o[nf], p, vf[nf]);
        }
    }

    // epilogue: divide by l (register-resident), store fp16 y
    {
        const float li0 = 1.0f / l0r;
        const float li1 = 1.0f / l1r;
        __half* y0 = y + ((size_t)(b * TT + q0 + r0)) * CC + h * HDD;
        __half* y1 = y + ((size_t)(b * TT + q0 + r0 + 8)) * CC + h * HDD;
#pragma unroll
        for (int nf = 0; nf < 8; nf++) {
            const int col = wn * 64 + nf * 8 + c * 2;
            *(uint32_t*)(y0 + col) = pack_h2(acc_o[nf][0] * li0, acc_o[nf][1] * li0);
            *(uint32_t*)(y1 + col) = pack_h2(acc_o[nf][2] * li1, acc_o[nf][3] * li1);
        }
    }
}

// ---------------------------------------------------------------------------
// Launch
// ---------------------------------------------------------------------------
extern "C" void kernel_launch(void* const* d_in, const int* in_sizes, int n_in,
                              void* d_out, int out_size)
{
    const float* x      = (const float*)d_in[0];   // [2,2048,2048]
    const float* w_att  = (const float*)d_in[1];   // [6144,2048]
    const float* b_att  = (const float*)d_in[2];   // [6144]
    const float* w_proj = (const float*)d_in[3];   // [2048,2048]
    const float* b_proj = (const float*)d_in[4];   // [2048]
    float* out = (float*)d_out;                    // [2,2048,2048]

    __half *qkvh, *yh, *xh, *wah, *wph;
    float2* rope;
    cudaGetSymbolAddress((void**)&qkvh, g_qkvh);
    cudaGetSymbolAddress((void**)&yh,   g_yh);
    cudaGetSymbolAddress((void**)&xh,   g_xh);
    cudaGetSymbolAddress((void**)&wah,  g_wah);
    cudaGetSymbolAddress((void**)&wph,  g_wph);
    cudaGetSymbolAddress((void**)&rope, g_rope);

    cudaFuncSetAttribute(gemm_h_kernel,
                         cudaFuncAttributeMaxDynamicSharedMemorySize,
                         GEMM_SMEM_BYTES);
    cudaFuncSetAttribute(flash_h_kernel,
                         cudaFuncAttributeMaxDynamicSharedMemorySize,
                         FLASH_SMEM_BYTES);

    // 0) Fused pre-pass: fp16 rounding of x/w_att/w_proj + rope table
    prep_kernel<<<(PREP_TOTAL + 255) / 256, 256>>>(
        (const float2*)x, (const float2*)w_att, (const float2*)w_proj,
        (__half2*)xh, (__half2*)wah, (__half2*)wph, rope);

    // 1) QKV projection + fused RoPE -> fp16 qkv
    gemm_h_kernel<<<dim3(NQKV / 128, MROWS / 128), 256, GEMM_SMEM_BYTES>>>(
        xh, wah, b_att, qkvh, rope, 1, MROWS, NQKV, CC);

    // 2) Causal flash attention -> yh [B,T,C] fp16
    flash_h_kernel<<<dim3(TT / 64, BB * NHH), 256, FLASH_SMEM_BYTES>>>(qkvh, yh);

    // 3) Output projection: out = y @ w_proj^T + b_proj (fp32 out)
    gemm_h_kernel<<<dim3(CC / 128, MROWS / 128), 256, GEMM_SMEM_BYTES>>>(
        yh, wph, b_proj, out, rope, 0, MROWS, CC, CC);
}

// round 17
// speedup vs baseline: 1.0444x; 1.0180x over previous
#include <cuda_runtime.h>
#include <cuda_fp16.h>
#include <math.h>
#include <stdint.h>

// Problem constants
#define BB     2
#define TT     2048
#define CC     2048
#define NHH    16
#define HDD    128
#define NQKV   6144          // 3*C
#define MROWS  4096          // B*T

// Scratch (device globals; no allocation allowed)
__device__ __half g_qkvh[(size_t)MROWS * NQKV];     // 48 MB (q,k roped; v raw)
__device__ __half g_yh[(size_t)MROWS * CC];         // 16 MB
__device__ __half g_xh[(size_t)MROWS * CC];         // 16 MB
__device__ __half g_wah[(size_t)NQKV * CC];         // 24 MB
__device__ __half g_wph[(size_t)CC * CC];           // 8 MB
__device__ float2 g_rope[TT * 64];                  // cos/sin table [t][i]

#define NEG_INF (__int_as_float(0xff800000))

// mma.sync m16n8k16 fp16 -> fp32 acc (in-place)
#define MMA_F16(d, a, b) \
    asm volatile("mma.sync.aligned.m16n8k16.row.col.f32.f16.f16.f32 " \
        "{%0,%1,%2,%3}, {%4,%5,%6,%7}, {%8,%9}, {%0,%1,%2,%3};" \
        : "+f"((d)[0]), "+f"((d)[1]), "+f"((d)[2]), "+f"((d)[3]) \
        : "r"((a)[0]), "r"((a)[1]), "r"((a)[2]), "r"((a)[3]), \
          "r"((b)[0]), "r"((b)[1]))

// ldmatrix x4 (non-transposed)
#define LDSM_X4(r0, r1, r2, r3, addr) \
    asm volatile("ldmatrix.sync.aligned.m8n8.x4.shared.b16 {%0,%1,%2,%3}, [%4];" \
        : "=r"(r0), "=r"(r1), "=r"(r2), "=r"(r3) : "r"(addr))

// ldmatrix x4 transposed (for V in [token][d] layout -> B fragments)
#define LDSM_X4_T(r0, r1, r2, r3, addr) \
    asm volatile("ldmatrix.sync.aligned.m8n8.x4.trans.shared.b16 {%0,%1,%2,%3}, [%4];" \
        : "=r"(r0), "=r"(r1), "=r"(r2), "=r"(r3) : "r"(addr))

__device__ __forceinline__ void cp_async16(uint32_t saddr, const void* gptr) {
    asm volatile("cp.async.cg.shared.global [%0], [%1], 16;"
                 :: "r"(saddr), "l"(gptr));
}
#define CP_COMMIT() asm volatile("cp.async.commit_group;" ::: "memory")
#define CP_WAIT(n)  asm volatile("cp.async.wait_group %0;" :: "n"(n) : "memory")

__device__ __forceinline__ uint32_t smem_u32(const void* p) {
    uint32_t a;
    asm("{ .reg .u64 t; cvta.to.shared.u64 t, %1; cvt.u32.u64 %0, t; }"
        : "=r"(a) : "l"(p));
    return a;
}

__device__ __forceinline__ uint32_t pack_h2(float lo, float hi) {
    __half2 h = __floats2half2_rn(lo, hi);
    return *(uint32_t*)&h;
}

// ---------------------------------------------------------------------------
// Fused pre-pass: fp32->fp16 rounding for x, w_att, w_proj + RoPE table.
// ---------------------------------------------------------------------------
#define NX2  (MROWS * CC / 2)
#define NWA2 (NQKV * CC / 2)
#define NWP2 (CC * CC / 2)
#define NRP  (TT * 64)
#define PREP_TOTAL (NX2 + NWA2 + NWP2 + NRP)

__global__ void prep_kernel(const float2* __restrict__ x,
                            const float2* __restrict__ wa,
                            const float2* __restrict__ wp,
                            __half2* __restrict__ xh,
                            __half2* __restrict__ wah,
                            __half2* __restrict__ wph,
                            float2* __restrict__ rope)
{
    int i = blockIdx.x * blockDim.x + threadIdx.x;
    if (i < NX2) {
        float2 v = x[i];
        xh[i] = __floats2half2_rn(v.x, v.y);
        return;
    }
    i -= NX2;
    if (i < NWA2) {
        float2 v = wa[i];
        wah[i] = __floats2half2_rn(v.x, v.y);
        return;
    }
    i -= NWA2;
    if (i < NWP2) {
        float2 v = wp[i];
        wph[i] = __floats2half2_rn(v.x, v.y);
        return;
    }
    i -= NWP2;
    if (i < NRP) {
        int tpos = i >> 6;
        int ii   = i & 63;
        float theta = 1.0f / powf(10000.0f, (float)ii / 64.0f);
        float ang   = (float)tpos * theta;
        float2 cs;
        cs.x = cosf(ang);
        cs.y = sinf(ang);
        rope[i] = cs;
    }
}

// ---------------------------------------------------------------------------
// FP16 tensor-core GEMM, cp.async 3-stage, CTA 128x128, warp 32x64, BK=64.
// ---------------------------------------------------------------------------
#define PITCH2 36                         // u32 per row (32 data + 4 pad)
#define TILE2_U32 (128 * PITCH2)
#define STAGE2_U32 (2 * TILE2_U32)
#define NSTAGE 3
#define GEMM_SMEM_BYTES (NSTAGE * STAGE2_U32 * 4)   // 110592

__global__ void __launch_bounds__(256, 2) gemm_h_kernel(
    const __half* __restrict__ A, const __half* __restrict__ W,
    const float* __restrict__ bias, void* __restrict__ outv,
    const float2* __restrict__ rope, int qkv_mode,
    int M, int N, int K)
{
    extern __shared__ __align__(16) uint32_t gsm[];
    const uint32_t sbase = smem_u32(gsm);

    const int t = threadIdx.x, lane = t & 31, wid = t >> 5;
    const int wm = wid & 3, wn = wid >> 2;
    const int g = lane >> 2, c = lane & 3;
    const int m0 = blockIdx.y * 128, n0 = blockIdx.x * 128;

    const int quad   = lane >> 3;
    const int lrow_a = (lane & 7) + ((quad & 1) << 3);
    const int kseg_a = (quad >> 1) << 2;
    const int lrow_b = (lane & 7) + ((quad >> 1) << 3);
    const int kseg_b = (quad & 1) << 2;

    const int lrow = t >> 3;             // loader row 0..31
    const int lch  = t & 7;              // loader 16B chunk

    const __half* Ab = A + (size_t)m0 * K;
    const __half* Wb = W + (size_t)n0 * K;

    float acc[2][8][4];
#pragma unroll
    for (int i = 0; i < 2; i++)
#pragma unroll
        for (int j = 0; j < 8; j++)
#pragma unroll
            for (int r = 0; r < 4; r++) acc[i][j][r] = 0.f;

    const int nsteps = K >> 6;           // BK = 64 halves

    auto issue_stage = [&](int s, int kk) {
        const uint32_t sA = sbase + (uint32_t)(s * STAGE2_U32) * 4;
        const uint32_t sB = sA + TILE2_U32 * 4;
        const int kof = kk * 64 + lch * 8;
#pragma unroll
        for (int i = 0; i < 4; i++) {
            const int row = lrow + i * 32;
            cp_async16(sA + (row * PITCH2 + lch * 4) * 4, Ab + (size_t)row * K + kof);
            cp_async16(sB + (row * PITCH2 + lch * 4) * 4, Wb + (size_t)row * K + kof);
        }
        CP_COMMIT();
    };

    issue_stage(0, 0);
    issue_stage(1, 1);

    for (int j = 0; j < nsteps; j++) {
        const int cur = j % NSTAGE;
        CP_WAIT(1);
        __syncthreads();    // stage j visible AND all warps done with buffer (j+2)%3
        if (j + 2 < nsteps) issue_stage((j + 2) % NSTAGE, j + 2);

        const uint32_t sAb = sbase + (uint32_t)(cur * STAGE2_U32) * 4;
        const uint32_t sBb = sAb + TILE2_U32 * 4;
#pragma unroll
        for (int ks = 0; ks < 4; ks++) {          // 4 x k16
            const int kc = ks * 8;
            uint32_t a[2][4];
#pragma unroll
            for (int mt = 0; mt < 2; mt++) {
                const uint32_t ad = sAb +
                    (uint32_t)(((wm * 32 + mt * 16 + lrow_a) * PITCH2) + kc + kseg_a) * 4;
                LDSM_X4(a[mt][0], a[mt][1], a[mt][2], a[mt][3], ad);
            }
            uint32_t bfr[8][2];
#pragma unroll
            for (int p = 0; p < 4; p++) {
                const uint32_t bd = sBb +
                    (uint32_t)(((wn * 64 + p * 16 + lrow_b) * PITCH2) + kc + kseg_b) * 4;
                LDSM_X4(bfr[2 * p][0], bfr[2 * p][1],
                        bfr[2 * p + 1][0], bfr[2 * p + 1][1], bd);
            }
#pragma unroll
            for (int mt = 0; mt < 2; mt++)
#pragma unroll
                for (int nf = 0; nf < 8; nf++)
                    MMA_F16(acc[mt][nf], a[mt], bfr[nf]);
        }
    }

    // epilogue
#pragma unroll
    for (int mt = 0; mt < 2; mt++) {
        const int r0 = m0 + wm * 32 + mt * 16 + g;
        const int tp0 = r0 & (TT - 1);
        const int tp1 = (r0 + 8) & (TT - 1);
#pragma unroll
        for (int nf = 0; nf < 8; nf++) {
            const int col = n0 + wn * 64 + nf * 8 + c * 2;
            const float b0v = bias[col], b1v = bias[col + 1];
            float v00 = acc[mt][nf][0] + b0v;
            float v01 = acc[mt][nf][1] + b1v;
            float v10 = acc[mt][nf][2] + b0v;
            float v11 = acc[mt][nf][3] + b1v;
            if (qkv_mode) {
                if (col < 2 * CC) {
                    const int i = (col & (HDD - 1)) >> 1;
                    const float2 cs0 = rope[tp0 * 64 + i];
                    const float2 cs1 = rope[tp1 * 64 + i];
                    float e0 = v00 * cs0.x - v01 * cs0.y;
                    float o0 = v00 * cs0.y + v01 * cs0.x;
                    float e1 = v10 * cs1.x - v11 * cs1.y;
                    float o1 = v10 * cs1.y + v11 * cs1.x;
                    v00 = e0; v01 = o0; v10 = e1; v11 = o1;
                }
                __half* outh = (__half*)outv;
                *(uint32_t*)(outh + (size_t)r0 * N + col)       = pack_h2(v00, v01);
                *(uint32_t*)(outh + (size_t)(r0 + 8) * N + col) = pack_h2(v10, v11);
            } else {
                float* outf = (float*)outv;
                float* o0p = outf + (size_t)r0 * N + col;
                float* o1p = outf + (size_t)(r0 + 8) * N + col;
                o0p[0] = v00; o0p[1] = v01;
                o1p[0] = v10; o1p[1] = v11;
            }
        }
    }
}

// ---------------------------------------------------------------------------
// Flash attention: Q-tile 64, KV-tile 128, 256 threads, 2 CTAs/SM.
// Single K buffer (next-K prefetch after QK frees it); V overlap retained.
// V natural [token][d] layout; PV B-frags via ldmatrix.trans.
// m/l softmax state register-resident. 3 syncs per 128 keys.
// ---------------------------------------------------------------------------
#define FQP2 68    // u32 pitch for Q/K/V rows (64 data + 4)
#define FSPI 68    // u32 pitch for P rows (64 data + 4; 128 keys fp16)
#define FL_Q_U32  (64 * FQP2)      // 4352
#define FL_K_U32  (128 * FQP2)     // 8704
#define FL_V_U32  (128 * FQP2)     // 8704
#define FL_S_U32  (64 * FSPI)      // 4352
#define FL_STATS  (4 * 64)         // pmax[2][64], psum[2][64]
#define FLASH_SMEM_U32 (FL_Q_U32 + FL_K_U32 + FL_V_U32 + FL_S_U32 + FL_STATS)
#define FLASH_SMEM_BYTES (FLASH_SMEM_U32 * 4)    // ~105.6 KB

__global__ void __launch_bounds__(256, 2) flash_h_kernel(
    const __half* __restrict__ qkvh, __half* __restrict__ y)
{
    extern __shared__ uint32_t fsm[];
    uint32_t* Ssu = fsm + FL_Q_U32 + FL_K_U32 + FL_V_U32;
    float* pmax = (float*)(Ssu + FL_S_U32);   // [2][64]
    float* psum = pmax + 2 * 64;              // [2][64]

    const uint32_t Qsb = smem_u32(fsm);
    const uint32_t Kb  = Qsb + FL_Q_U32 * 4;
    const uint32_t Vb  = Kb + FL_K_U32 * 4;
    const uint32_t Ssb = Vb + FL_V_U32 * 4;

    const int bh = blockIdx.y, b = bh >> 4, h = bh & 15;
    const int qt = gridDim.x - 1 - blockIdx.x;    // heavy tiles first
    const int q0 = qt * 64;
    const int t = threadIdx.x, lane = t & 31, wid = t >> 5;
    const int wm = wid & 3, wn = wid >> 2;
    const int g = lane >> 2, c = lane & 3;
    const float scale = 0.08838834764831845f;   // 1/sqrt(128)

    const int quad   = lane >> 3;
    const int lrow_a = (lane & 7) + ((quad & 1) << 3);
    const int kseg_a = (quad >> 1) << 2;
    const int lrow_b = (lane & 7) + ((quad >> 1) << 3);
    const int kseg_b = (quad & 1) << 2;

    // trans-ldmatrix lane mapping for V [token][d]
    const int vrow = lane & 15;
    const int vseg = (lane >> 4) << 2;

    const __half* Qg = qkvh + ((size_t)(b * TT + q0)) * NQKV + h * HDD;
    const __half* Kbase = qkvh + (size_t)b * TT * NQKV + CC + h * HDD;
    const __half* Vbase = Kbase + CC;

    // load Q tile + K(0) tile via cp.async
#pragma unroll
    for (int i = 0; i < 4; i++) {
        const int idx = t + i * 256;
        const int rr = idx >> 4, cc = idx & 15;
        cp_async16(Qsb + (rr * FQP2 + cc * 4) * 4,
                   Qg + (size_t)rr * NQKV + cc * 8);
    }
    CP_COMMIT();
#pragma unroll
    for (int i = 0; i < 8; i++) {      // K tile: 128 rows x 16 chunks
        const int idx = t + i * 256;
        const int rr = idx >> 4, cc = idx & 15;
        cp_async16(Kb + (rr * FQP2 + cc * 4) * 4,
                   Kbase + (size_t)rr * NQKV + cc * 8);
    }
    CP_COMMIT();

    const int r0 = wm * 16 + g;
    const int qg0 = q0 + r0, qg1 = q0 + r0 + 8;

    // register-resident softmax state (rows r0 and r0+8)
    float m0r = NEG_INF, m1r = NEG_INF;
    float l0r = 0.f, l1r = 0.f;

    float acc_o[8][4];
#pragma unroll
    for (int j = 0; j < 8; j++)
#pragma unroll
        for (int r = 0; r < 4; r++) acc_o[j][r] = 0.f;

    const int nkt = (qt + 2) >> 1;     // 128-key tiles covering q0+63
    for (int kt = 0; kt < nkt; kt++) {
        const int k0 = kt * 128;

        CP_WAIT(0);                    // K(kt) (and Q on iter 0) arrived
        __syncthreads();               // visible to all; prev iter done with V/Ss

        // S = Q K^T : warp computes 16 rows x 64 keys (wn half of 128)
        float acc_s[8][4];
#pragma unroll
        for (int j = 0; j < 8; j++)
#pragma unroll
            for (int r = 0; r < 4; r++) acc_s[j][r] = 0.f;
#pragma unroll
        for (int ks = 0; ks < 8; ks++) {
            const int kc = ks * 8;
            uint32_t a[4];
            {
                const uint32_t ad = Qsb +
                    (uint32_t)(((wm * 16 + lrow_a) * FQP2) + kc + kseg_a) * 4;
                LDSM_X4(a[0], a[1], a[2], a[3], ad);
            }
            uint32_t bf[8][2];
#pragma unroll
            for (int p = 0; p < 4; p++) {
                const uint32_t bd = Kb +
                    (uint32_t)(((wn * 64 + p * 16 + lrow_b) * FQP2) + kc + kseg_b) * 4;
                LDSM_X4(bf[2 * p][0], bf[2 * p][1],
                        bf[2 * p + 1][0], bf[2 * p + 1][1], bd);
            }
#pragma unroll
            for (int nf = 0; nf < 8; nf++)
                MMA_F16(acc_s[nf], a, bf[nf]);
        }

        // scale + causal mask
#pragma unroll
        for (int nf = 0; nf < 8; nf++) {
            const int kg0 = k0 + wn * 64 + nf * 8 + c * 2;
            acc_s[nf][0] = (kg0     <= qg0) ? acc_s[nf][0] * scale : NEG_INF;
            acc_s[nf][1] = (kg0 + 1 <= qg0) ? acc_s[nf][1] * scale : NEG_INF;
            acc_s[nf][2] = (kg0     <= qg1) ? acc_s[nf][2] * scale : NEG_INF;
            acc_s[nf][3] = (kg0 + 1 <= qg1) ? acc_s[nf][3] * scale : NEG_INF;
        }

        // warp-level row max over this warp's 64 keys
        float mx0 = NEG_INF, mx1 = NEG_INF;
#pragma unroll
        for (int nf = 0; nf < 8; nf++) {
            mx0 = fmaxf(mx0, fmaxf(acc_s[nf][0], acc_s[nf][1]));
            mx1 = fmaxf(mx1, fmaxf(acc_s[nf][2], acc_s[nf][3]));
        }
        mx0 = fmaxf(mx0, __shfl_xor_sync(0xffffffffu, mx0, 1));
        mx0 = fmaxf(mx0, __shfl_xor_sync(0xffffffffu, mx0, 2));
        mx1 = fmaxf(mx1, __shfl_xor_sync(0xffffffffu, mx1, 1));
        mx1 = fmaxf(mx1, __shfl_xor_sync(0xffffffffu, mx1, 2));
        if (c == 0) {
            pmax[wn * 64 + r0]     = mx0;
            pmax[wn * 64 + r0 + 8] = mx1;
        }
        __syncthreads();               // pmax ready; K buffer free after QK

        // issue V(kt) load, then prefetch K(kt+1) into the (now free) K buffer
        {
            const __half* Vg = Vbase + (size_t)k0 * NQKV;
#pragma unroll
            for (int i = 0; i < 8; i++) {
                const int idx = t + i * 256;
                const int rr = idx >> 4, cc = idx & 15;
                cp_async16(Vb + (rr * FQP2 + cc * 4) * 4,
                           Vg + (size_t)rr * NQKV + cc * 8);
            }
            CP_COMMIT();
        }
        if (kt + 1 < nkt) {
            const __half* Kn = Kbase + (size_t)(k0 + 128) * NQKV;
#pragma unroll
            for (int i = 0; i < 8; i++) {
                const int idx = t + i * 256;
                const int rr = idx >> 4, cc = idx & 15;
                cp_async16(Kb + (rr * FQP2 + cc * 4) * 4,
                           Kn + (size_t)rr * NQKV + cc * 8);
            }
            CP_COMMIT();
        }

        // combine max, exp, partial sums, write P (fp16)
        const float mnew0 = fmaxf(m0r, fmaxf(pmax[r0], pmax[64 + r0]));
        const float mnew1 = fmaxf(m1r, fmaxf(pmax[r0 + 8], pmax[64 + r0 + 8]));
        const float f0 = __expf(m0r - mnew0);
        const float f1 = __expf(m1r - mnew1);
        m0r = mnew0;
        m1r = mnew1;

        float s0 = 0.f, s1 = 0.f;
#pragma unroll
        for (int nf = 0; nf < 8; nf++) {
            const int cu = wn * 32 + nf * 4 + c;
            float p00 = __expf(acc_s[nf][0] - mnew0);
            float p01 = __expf(acc_s[nf][1] - mnew0);
            float p10 = __expf(acc_s[nf][2] - mnew1);
            float p11 = __expf(acc_s[nf][3] - mnew1);
            s0 += p00 + p01;
            s1 += p10 + p11;
            Ssu[r0 * FSPI + cu]       = pack_h2(p00, p01);
            Ssu[(r0 + 8) * FSPI + cu] = pack_h2(p10, p11);
        }
        s0 += __shfl_xor_sync(0xffffffffu, s0, 1);
        s0 += __shfl_xor_sync(0xffffffffu, s0, 2);
        s1 += __shfl_xor_sync(0xffffffffu, s1, 1);
        s1 += __shfl_xor_sync(0xffffffffu, s1, 2);
        if (c == 0) {
            psum[wn * 64 + r0]     = s0;
            psum[wn * 64 + r0 + 8] = s1;
        }
        if (kt + 1 < nkt) { CP_WAIT(1); }   // V done; K(kt+1) may still fly
        else              { CP_WAIT(0); }
        __syncthreads();               // V + P + psum visible

        // l update (register-resident)
        l0r = l0r * f0 + psum[r0]     + psum[64 + r0];
        l1r = l1r * f1 + psum[r0 + 8] + psum[64 + r0 + 8];

#pragma unroll
        for (int nf = 0; nf < 8; nf++) {
            acc_o[nf][0] *= f0; acc_o[nf][1] *= f0;
            acc_o[nf][2] *= f1; acc_o[nf][3] *= f1;
        }

        // O += P V   (8 x k16 token-chunks; V B-frags via ldmatrix.trans)
#pragma unroll
        for (int ks = 0; ks < 8; ks++) {
            const int kc = ks * 8;
            uint32_t p[4];
            {
                const uint32_t pd = Ssb +
                    (uint32_t)(((wm * 16 + lrow_a) * FSPI) + kc + kseg_a) * 4;
                LDSM_X4(p[0], p[1], p[2], p[3], pd);
            }
            uint32_t vf[8][2];
#pragma unroll
            for (int db = 0; db < 4; db++) {
                const uint32_t vd = Vb +
                    (uint32_t)(((ks * 16 + vrow) * FQP2) + wn * 32 + db * 8 + vseg) * 4;
                LDSM_X4_T(vf[2 * db][0], vf[2 * db][1],
                          vf[2 * db + 1][0], vf[2 * db + 1][1], vd);
            }
#pragma unroll
            for (int nf = 0; nf < 8; nf++)
                MMA_F16(acc_o[nf], p, vf[nf]);
        }
    }

    // epilogue: divide by l (register-resident), store fp16 y
    {
        const float li0 = 1.0f / l0r;
        const float li1 = 1.0f / l1r;
        __half* y0 = y + ((size_t)(b * TT + q0 + r0)) * CC + h * HDD;
        __half* y1 = y + ((size_t)(b * TT + q0 + r0 + 8)) * CC + h * HDD;
#pragma unroll
        for (int nf = 0; nf < 8; nf++) {
            const int col = wn * 64 + nf * 8 + c * 2;
            *(uint32_t*)(y0 + col) = pack_h2(acc_o[nf][0] * li0, acc_o[nf][1] * li0);
            *(uint32_t*)(y1 + col) = pack_h2(acc_o[nf][2] * li1, acc_o[nf][3] * li1);
        }
    }
}

// ---------------------------------------------------------------------------
// Launch
// ---------------------------------------------------------------------------
extern "C" void kernel_launch(void* const* d_in, const int* in_sizes, int n_in,
                              void* d_out, int out_size)
{
    const float* x      = (const float*)d_in[0];   // [2,2048,2048]
    const float* w_att  = (const float*)d_in[1];   // [6144,2048]
    const float* b_att  = (const float*)d_in[2];   // [6144]
    const float* w_proj = (const float*)d_in[3];   // [2048,2048]
    const float* b_proj = (const float*)d_in[4];   // [2048]
    float* out = (float*)d_out;                    // [2,2048,2048]

    __half *qkvh, *yh, *xh, *wah, *wph;
    float2* rope;
    cudaGetSymbolAddress((void**)&qkvh, g_qkvh);
    cudaGetSymbolAddress((void**)&yh,   g_yh);
    cudaGetSymbolAddress((void**)&xh,   g_xh);
    cudaGetSymbolAddress((void**)&wah,  g_wah);
    cudaGetSymbolAddress((void**)&wph,  g_wph);
    cudaGetSymbolAddress((void**)&rope, g_rope);

    cudaFuncSetAttribute(gemm_h_kernel,
                         cudaFuncAttributeMaxDynamicSharedMemorySize,
                         GEMM_SMEM_BYTES);
    cudaFuncSetAttribute(flash_h_kernel,
                         cudaFuncAttributeMaxDynamicSharedMemorySize,
                         FLASH_SMEM_BYTES);

    // 0) Fused pre-pass: fp16 rounding of x/w_att/w_proj + rope table
    prep_kernel<<<(PREP_TOTAL + 255) / 256, 256>>>(
        (const float2*)x, (const float2*)w_att, (const float2*)w_proj,
        (__half2*)xh, (__half2*)wah, (__half2*)wph, rope);

    // 1) QKV projection + fused RoPE -> fp16 qkv
    gemm_h_kernel<<<dim3(NQKV / 128, MROWS / 128), 256, GEMM_SMEM_BYTES>>>(
        xh, wah, b_att, qkvh, rope, 1, MROWS, NQKV, CC);

    // 2) Causal flash attention -> yh [B,T,C] fp16
    flash_h_kernel<<<dim3(TT / 64, BB * NHH), 256, FLASH_SMEM_BYTES>>>(qkvh, yh);

    // 3) Output projection: out = y @ w_proj^T + b_proj (fp32 out)
    gemm_h_kernel<<<dim3(CC / 128, MROWS / 128), 256, GEMM_SMEM_BYTES>>>(
        yh, wph, b_proj, out, rope, 0, MROWS, CC, CC);
}